// round 3
// baseline (speedup 1.0000x reference)
#include <cuda_runtime.h>
#include <math.h>

#define BB   32
#define NN   100
#define HH   128
#define BIN  16
#define EE   20000

typedef unsigned long long u64;

// Scratch (allocation-free rule: __device__ globals)
__device__ float d_P[BB * NN * HH];   // P[b,n,k] = lf[b,n]·W_apair[:,k] + 0.5*b_binary[k]
__device__ float d_G[BB * NN * HH];   // global_feats[b,i,h]

// ---- packed f32x2 helpers (Blackwell FFMA2 path; b64 containers) ----------
__device__ __forceinline__ u64 fma2(u64 a, u64 b, u64 c) {
    u64 d; asm("fma.rn.f32x2 %0, %1, %2, %3;" : "=l"(d) : "l"(a), "l"(b), "l"(c));
    return d;
}
__device__ __forceinline__ u64 add2(u64 a, u64 b) {
    u64 d; asm("add.rn.f32x2 %0, %1, %2;" : "=l"(d) : "l"(a), "l"(b));
    return d;
}
__device__ __forceinline__ u64 pack2(float lo, float hi) {
    u64 d; asm("mov.b64 %0, {%1, %2};" : "=l"(d) : "f"(lo), "f"(hi));
    return d;
}
__device__ __forceinline__ void unpack2(u64 v, float& lo, float& hi) {
    asm("mov.b64 {%0, %1}, %2;" : "=f"(lo), "=f"(hi) : "l"(v));
}

// ---------------------------------------------------------------------------
// Kernel A: P[b,n,k] = sum_h lf[b,n,h] * Wap[h,k] + 0.5*bb[k]
// 16 rows per block (grid 200), thread = column k, 16 register accumulators.
// Wap element loaded once per block and reused x16.
// ---------------------------------------------------------------------------
#define RA 16
__global__ __launch_bounds__(128) void kA(const float* __restrict__ lf,
                                          const float* __restrict__ Wap,
                                          const float* __restrict__ bb) {
    const int r0 = blockIdx.x * RA;       // first (b,n) row of this block
    const int k  = threadIdx.x;

    __shared__ float4 row[RA][HH / 4];    // 8 KB of lf rows

    const float4* lsrc = (const float4*)(lf + (size_t)r0 * HH);
    #pragma unroll
    for (int t = k; t < RA * HH / 4; t += 128) ((float4*)row)[t] = lsrc[t];
    __syncthreads();

    float acc[RA];
    const float binit = 0.5f * bb[k];
    #pragma unroll
    for (int r = 0; r < RA; ++r) acc[r] = binit;

    for (int h = 0; h < HH; h += 4) {
        const float w0 = Wap[(h + 0) * HH + k];
        const float w1 = Wap[(h + 1) * HH + k];
        const float w2 = Wap[(h + 2) * HH + k];
        const float w3 = Wap[(h + 3) * HH + k];
        #pragma unroll
        for (int r = 0; r < RA; ++r) {
            const float4 rv = row[r][h >> 2];        // broadcast LDS.128
            acc[r] = fmaf(rv.x, w0, acc[r]);
            acc[r] = fmaf(rv.y, w1, acc[r]);
            acc[r] = fmaf(rv.z, w2, acc[r]);
            acc[r] = fmaf(rv.w, w3, acc[r]);
        }
    }
    #pragma unroll
    for (int r = 0; r < RA; ++r) d_P[(size_t)(r0 + r) * HH + k] = acc[r];
}

// ---------------------------------------------------------------------------
// Kernel B: per (b,i): att scores over j + global_feats accumulation.
// One block per (b,i); 4 warps; warp w handles j = w, w+4, ...
// Lane l owns k in {4l..4l+3} as TWO packed f32x2 accumulators.
// bin features staged in SMEM PRE-DUPLICATED as (v,v) b64 words so the
// inner loop is LDS.64-broadcast + FFMA2 with no per-iter packing.
// ---------------------------------------------------------------------------
__global__ __launch_bounds__(128) void kB(const float* __restrict__ lf,
                                          const float* __restrict__ bin,
                                          const float* __restrict__ Wb,
                                          const float* __restrict__ Watt,
                                          const float* __restrict__ batt) {
    const int bi  = blockIdx.x;            // b*NN + i
    const int tid = threadIdx.x;
    const int w   = tid >> 5;
    const int l   = tid & 31;
    const int k0  = l << 2;

    __shared__ u64   bin_dup[NN][BIN];     // 12.8 KB: bin_dup[j][c] = (v,v)
    __shared__ float red[4][HH];           // cross-warp g reduction

    // Stage bin[b,i,:,:] duplicated (coalesced float4 reads)
    {
        const float4* src = (const float4*)(bin + (size_t)bi * NN * BIN);
        for (int t = tid; t < NN * BIN / 4; t += 128) {
            const float4 v = src[t];
            const int j  = t >> 2;          // t / (BIN/4)
            const int c4 = (t & 3) << 2;
            bin_dup[j][c4 + 0] = pack2(v.x, v.x);
            bin_dup[j][c4 + 1] = pack2(v.y, v.y);
            bin_dup[j][c4 + 2] = pack2(v.z, v.z);
            bin_dup[j][c4 + 3] = pack2(v.w, v.w);
        }
    }

    // W_binary column quads as packed pairs: wb01[c]=(w[k0],w[k0+1]), wb23=(w[k0+2],w[k0+3])
    u64 wb01[BIN], wb23[BIN];
    #pragma unroll
    for (int c = 0; c < BIN; ++c) {
        const ulonglong2 v = *(const ulonglong2*)(Wb + c * HH + k0);
        wb01[c] = v.x; wb23[c] = v.y;
    }
    const float4 wa    = *(const float4*)(Watt + k0);
    const float  batt0 = batt[0];

    const int    b     = bi / NN;
    const float* Pbase = d_P + (size_t)b * NN * HH;
    const float* Lbase = lf  + (size_t)b * NN * HH;
    const ulonglong2 piv = *(const ulonglong2*)(d_P + (size_t)bi * HH + k0);

    u64 g01 = 0ULL, g23 = 0ULL;            // fp32x2 zeros (bit pattern 0 == +0.f,+0.f)

    __syncthreads();   // bin_dup ready

    for (int j = w; j < NN; j += 4) {
        const ulonglong2 pjv = *(const ulonglong2*)(Pbase + (size_t)j * HH + k0);
        const ulonglong2 ljv = *(const ulonglong2*)(Lbase + (size_t)j * HH + k0);

        u64 f01 = add2(piv.x, pjv.x);
        u64 f23 = add2(piv.y, pjv.y);
        #pragma unroll
        for (int c = 0; c < BIN; ++c) {
            const u64 bc = bin_dup[j][c];   // LDS.64 broadcast
            f01 = fma2(bc, wb01[c], f01);
            f23 = fma2(bc, wb23[c], f23);
        }

        float f0, f1, f2, f3;
        unpack2(f01, f0, f1);
        unpack2(f23, f2, f3);
        f0 = fmaxf(f0, 0.f); f1 = fmaxf(f1, 0.f);
        f2 = fmaxf(f2, 0.f); f3 = fmaxf(f3, 0.f);

        float part = f0 * wa.x + f1 * wa.y + f2 * wa.z + f3 * wa.w;
        #pragma unroll
        for (int o = 16; o > 0; o >>= 1)
            part += __shfl_xor_sync(0xFFFFFFFFu, part, o);

        const float s  = 1.f / (1.f + __expf(-(part + batt0)));
        const u64   s2 = pack2(s, s);

        g01 = fma2(s2, ljv.x, g01);
        g23 = fma2(s2, ljv.y, g23);
    }

    float g0, g1, g2, g3;
    unpack2(g01, g0, g1);
    unpack2(g23, g2, g3);
    red[w][k0 + 0] = g0;
    red[w][k0 + 1] = g1;
    red[w][k0 + 2] = g2;
    red[w][k0 + 3] = g3;
    __syncthreads();
    d_G[(size_t)bi * HH + tid] =
        (red[0][tid] + red[1][tid]) + (red[2][tid] + red[3][tid]);
}

// ---------------------------------------------------------------------------
// Kernel C: gather epilogue (float4, BW-bound).
// warp 0: local_pair_g, warp 1: global_pair.
// ---------------------------------------------------------------------------
__global__ __launch_bounds__(64) void kC(const float* __restrict__ lf,
                                         const int* __restrict__ idx,
                                         float* __restrict__ out) {
    const int e    = blockIdx.x;
    const int half = threadIdx.x >> 5;
    const int lane = threadIdx.x & 31;

    int b = idx[e * 3 + 0];
    int i = idx[e * 3 + 1];
    int j = idx[e * 3 + 2];
    b = min(max(b, 0), BB - 1);
    i = min(max(i, 0), NN - 1);
    j = min(max(j, 0), NN - 1);

    const size_t ri = ((size_t)b * NN + i) * (HH / 4);
    const size_t rj = ((size_t)b * NN + j) * (HH / 4);
    float4* o = (float4*)out;

    if (half == 0) {
        const float4* L = (const float4*)lf;
        const float4 a = L[ri + lane], c = L[rj + lane];
        float4 r; r.x = a.x + c.x; r.y = a.y + c.y; r.z = a.z + c.z; r.w = a.w + c.w;
        o[(size_t)e * 32 + lane] = r;
    } else {
        const float4* G4 = (const float4*)d_G;
        const float4 a = G4[ri + lane], c = G4[rj + lane];
        float4 r; r.x = a.x + c.x; r.y = a.y + c.y; r.z = a.z + c.z; r.w = a.w + c.w;
        o[(size_t)EE * 32 + (size_t)e * 32 + lane] = r;
    }
}

// ---------------------------------------------------------------------------
extern "C" void kernel_launch(void* const* d_in, const int* in_sizes, int n_in,
                              void* d_out, int out_size) {
    const float* lf   = (const float*)d_in[0];   // [B,N,H]
    const float* bin  = (const float*)d_in[1];   // [B,N,N,BIN]
    const int*   sidx = (const int*)d_in[2];     // [E,3] int32
    const float* Wap  = (const float*)d_in[3];   // [H,H]
    const float* Wb   = (const float*)d_in[4];   // [BIN,H]
    const float* bb   = (const float*)d_in[5];   // [H]
    const float* Watt = (const float*)d_in[6];   // [H,1]
    const float* batt = (const float*)d_in[7];   // [1]
    float*       out  = (float*)d_out;

    kA<<<BB * NN / RA, 128>>>(lf, Wap, bb);
    kB<<<BB * NN, 128>>>(lf, bin, Wb, Watt, batt);
    kC<<<EE, 64>>>(lf, sidx, out);
}

// round 4
// speedup vs baseline: 1.1202x; 1.1202x over previous
#include <cuda_runtime.h>
#include <math.h>

#define BB   32
#define NN   100
#define HH   128
#define BIN  16
#define EE   20000

// Scratch (allocation-free rule: __device__ globals)
__device__ float d_P[BB * NN * HH];   // P[b,n,k] = lf[b,n]·W_apair[:,k] + 0.5*b_binary[k]
__device__ float d_G[BB * NN * HH];   // global_feats[b,i,h]

// ---------------------------------------------------------------------------
// Kernel A: P[b,n,k] = sum_h lf[b,n,h] * Wap[h,k] + 0.5*bb[k]
// 8 rows per block, split-K across two 128-thread halves (grid 400, block 256).
// Wap reuse x8 (25 MB L2 traffic total), 8 warps/block for latency hiding.
// ---------------------------------------------------------------------------
#define RA 8
__global__ __launch_bounds__(256) void kA(const float* __restrict__ lf,
                                          const float* __restrict__ Wap,
                                          const float* __restrict__ bb) {
    const int r0   = blockIdx.x * RA;
    const int tid  = threadIdx.x;
    const int k    = tid & (HH - 1);
    const int half = tid >> 7;            // 0: h in [0,64), 1: h in [64,128)

    __shared__ float row[RA][HH];         // 4 KB staged lf rows
    __shared__ float part[2][RA][HH];     // 8 KB split-K partials

    {
        const float4* lsrc = (const float4*)(lf + (size_t)r0 * HH);
        for (int t = tid; t < RA * HH / 4; t += 256) ((float4*)row)[t] = lsrc[t];
    }
    __syncthreads();

    float acc[RA];
    const float binit = (half == 0) ? 0.5f * bb[k] : 0.f;
    #pragma unroll
    for (int r = 0; r < RA; ++r) acc[r] = binit;

    const int h0 = half * (HH / 2);
    #pragma unroll 4
    for (int h = h0; h < h0 + HH / 2; ++h) {
        const float wv = Wap[h * HH + k];
        #pragma unroll
        for (int r = 0; r < RA; ++r)
            acc[r] = fmaf(row[r][h], wv, acc[r]);   // LDS broadcast
    }
    #pragma unroll
    for (int r = 0; r < RA; ++r) part[half][r][k] = acc[r];
    __syncthreads();

    // 256 threads write 1024 outputs (4 each)
    #pragma unroll
    for (int t = tid; t < RA * HH; t += 256) {
        const int r = t >> 7, kk = t & (HH - 1);
        d_P[(size_t)(r0 + r) * HH + t - (r << 7) + 0] = 0.f; // placeholder avoided below
    }
    // (rewrite cleanly)
    #pragma unroll
    for (int t = tid; t < RA * HH; t += 256) {
        const int r = t >> 7, kk = t & (HH - 1);
        d_P[(size_t)(r0 + r) * HH + kk] = part[0][r][kk] + part[1][r][kk];
    }
}

// ---------------------------------------------------------------------------
// Kernel B: per (b,i): att scores over j + global_feats accumulation.
// One block per (b,i); 4 warps; warp w owns j = w, w+4, ... (25 values),
// processed TWO at a time (j and j+4) for MLP/ILP. Lane l owns k=4l..4l+3.
// W_binary column quad (64 regs) shared by both in-flight j's.
// ---------------------------------------------------------------------------
__global__ __launch_bounds__(128) void kB(const float* __restrict__ lf,
                                          const float* __restrict__ bin,
                                          const float* __restrict__ Wb,
                                          const float* __restrict__ Watt,
                                          const float* __restrict__ batt) {
    const int bi  = blockIdx.x;            // b*NN + i
    const int tid = threadIdx.x;
    const int w   = tid >> 5;
    const int l   = tid & 31;
    const int k0  = l << 2;

    __shared__ float4 bin_sh[NN * BIN / 4];   // 6.4 KB
    __shared__ float  red[4][HH];

    {
        const float4* src = (const float4*)(bin + (size_t)bi * NN * BIN);
        for (int t = tid; t < NN * BIN / 4; t += 128) bin_sh[t] = src[t];
    }

    float wb[BIN][4];
    #pragma unroll
    for (int c = 0; c < BIN; ++c) {
        float4 v = *(const float4*)(Wb + c * HH + k0);
        wb[c][0] = v.x; wb[c][1] = v.y; wb[c][2] = v.z; wb[c][3] = v.w;
    }
    const float4 wa    = *(const float4*)(Watt + k0);
    const float  batt0 = batt[0];

    const int    b     = bi / NN;
    const float* Pbase = d_P + (size_t)b * NN * HH;
    const float* Lbase = lf  + (size_t)b * NN * HH;
    const float4 pi    = *(const float4*)(d_P + (size_t)bi * HH + k0);

    float g0 = 0.f, g1 = 0.f, g2 = 0.f, g3 = 0.f;

    __syncthreads();

    // Pairs (w+8t, w+8t+4) for t=0..11, tail j=w+96.
    for (int j = w; j < NN; j += 8) {
        const int  jA = j, jB = j + 4;
        const bool hasB = (jB < NN);

        const float4 pjA = *(const float4*)(Pbase + (size_t)jA * HH + k0);
        const float4 ljA = *(const float4*)(Lbase + (size_t)jA * HH + k0);
        float4 pjB = pjA, ljB = ljA;
        if (hasB) {
            pjB = *(const float4*)(Pbase + (size_t)jB * HH + k0);
            ljB = *(const float4*)(Lbase + (size_t)jB * HH + k0);
        }

        float a0 = pi.x + pjA.x, a1 = pi.y + pjA.y;
        float a2 = pi.z + pjA.z, a3 = pi.w + pjA.w;
        float e0 = pi.x + pjB.x, e1 = pi.y + pjB.y;
        float e2 = pi.z + pjB.z, e3 = pi.w + pjB.w;

        const float* bcA = (const float*)&bin_sh[jA * 4];
        const float* bcB = (const float*)&bin_sh[jB * 4];
        #pragma unroll
        for (int c = 0; c < BIN; ++c) {
            const float vA = bcA[c];                 // LDS broadcast
            const float vB = hasB ? bcB[c] : 0.f;
            a0 = fmaf(vA, wb[c][0], a0);
            e0 = fmaf(vB, wb[c][0], e0);
            a1 = fmaf(vA, wb[c][1], a1);
            e1 = fmaf(vB, wb[c][1], e1);
            a2 = fmaf(vA, wb[c][2], a2);
            e2 = fmaf(vB, wb[c][2], e2);
            a3 = fmaf(vA, wb[c][3], a3);
            e3 = fmaf(vB, wb[c][3], e3);
        }
        a0 = fmaxf(a0, 0.f); a1 = fmaxf(a1, 0.f);
        a2 = fmaxf(a2, 0.f); a3 = fmaxf(a3, 0.f);
        e0 = fmaxf(e0, 0.f); e1 = fmaxf(e1, 0.f);
        e2 = fmaxf(e2, 0.f); e3 = fmaxf(e3, 0.f);

        float pA = a0 * wa.x + a1 * wa.y + a2 * wa.z + a3 * wa.w;
        float pB = e0 * wa.x + e1 * wa.y + e2 * wa.z + e3 * wa.w;
        #pragma unroll
        for (int o = 16; o > 0; o >>= 1) {
            pA += __shfl_xor_sync(0xFFFFFFFFu, pA, o);
            pB += __shfl_xor_sync(0xFFFFFFFFu, pB, o);
        }

        const float sA = 1.f / (1.f + __expf(-(pA + batt0)));
        const float sB = 1.f / (1.f + __expf(-(pB + batt0)));

        g0 = fmaf(sA, ljA.x, g0);
        g1 = fmaf(sA, ljA.y, g1);
        g2 = fmaf(sA, ljA.z, g2);
        g3 = fmaf(sA, ljA.w, g3);
        if (hasB) {
            g0 = fmaf(sB, ljB.x, g0);
            g1 = fmaf(sB, ljB.y, g1);
            g2 = fmaf(sB, ljB.z, g2);
            g3 = fmaf(sB, ljB.w, g3);
        }
    }

    red[w][k0 + 0] = g0;
    red[w][k0 + 1] = g1;
    red[w][k0 + 2] = g2;
    red[w][k0 + 3] = g3;
    __syncthreads();
    d_G[(size_t)bi * HH + tid] =
        (red[0][tid] + red[1][tid]) + (red[2][tid] + red[3][tid]);
}

// ---------------------------------------------------------------------------
// Kernel C: gather epilogue (float4, BW-bound).
// ---------------------------------------------------------------------------
__global__ __launch_bounds__(64) void kC(const float* __restrict__ lf,
                                         const int* __restrict__ idx,
                                         float* __restrict__ out) {
    const int e    = blockIdx.x;
    const int half = threadIdx.x >> 5;
    const int lane = threadIdx.x & 31;

    int b = idx[e * 3 + 0];
    int i = idx[e * 3 + 1];
    int j = idx[e * 3 + 2];
    b = min(max(b, 0), BB - 1);
    i = min(max(i, 0), NN - 1);
    j = min(max(j, 0), NN - 1);

    const size_t ri = ((size_t)b * NN + i) * (HH / 4);
    const size_t rj = ((size_t)b * NN + j) * (HH / 4);
    float4* o = (float4*)out;

    if (half == 0) {
        const float4* L = (const float4*)lf;
        const float4 a = L[ri + lane], c = L[rj + lane];
        float4 r; r.x = a.x + c.x; r.y = a.y + c.y; r.z = a.z + c.z; r.w = a.w + c.w;
        o[(size_t)e * 32 + lane] = r;
    } else {
        const float4* G4 = (const float4*)d_G;
        const float4 a = G4[ri + lane], c = G4[rj + lane];
        float4 r; r.x = a.x + c.x; r.y = a.y + c.y; r.z = a.z + c.z; r.w = a.w + c.w;
        o[(size_t)EE * 32 + (size_t)e * 32 + lane] = r;
    }
}

// ---------------------------------------------------------------------------
extern "C" void kernel_launch(void* const* d_in, const int* in_sizes, int n_in,
                              void* d_out, int out_size) {
    const float* lf   = (const float*)d_in[0];   // [B,N,H]
    const float* bin  = (const float*)d_in[1];   // [B,N,N,BIN]
    const int*   sidx = (const int*)d_in[2];     // [E,3] int32
    const float* Wap  = (const float*)d_in[3];   // [H,H]
    const float* Wb   = (const float*)d_in[4];   // [BIN,H]
    const float* bb   = (const float*)d_in[5];   // [H]
    const float* Watt = (const float*)d_in[6];   // [H,1]
    const float* batt = (const float*)d_in[7];   // [1]
    float*       out  = (float*)d_out;

    kA<<<BB * NN / RA, 256>>>(lf, Wap, bb);
    kB<<<BB * NN, 128>>>(lf, bin, Wb, Watt, batt);
    kC<<<EE, 64>>>(lf, sidx, out);
}

// round 5
// speedup vs baseline: 1.1471x; 1.0241x over previous
#include <cuda_runtime.h>
#include <math.h>

#define BB   32
#define NN   100
#define HH   128
#define BIN  16
#define EE   20000

typedef unsigned long long u64;

// Scratch (allocation-free rule: __device__ globals)
__device__ float d_P[BB * NN * HH];   // P[b,n,k] = lf[b,n]·W_apair[:,k] + 0.5*b_binary[k]
__device__ float d_G[BB * NN * HH];   // global_feats[b,i,h]

// ---- packed f32x2 helpers (native on sm_100a, PTX ISA 8.6) ----------------
__device__ __forceinline__ u64 fma2(u64 a, u64 b, u64 c) {
    u64 d; asm("fma.rn.f32x2 %0, %1, %2, %3;" : "=l"(d) : "l"(a), "l"(b), "l"(c));
    return d;
}
__device__ __forceinline__ u64 add2(u64 a, u64 b) {
    u64 d; asm("add.rn.f32x2 %0, %1, %2;" : "=l"(d) : "l"(a), "l"(b));
    return d;
}
__device__ __forceinline__ u64 pack2(float lo, float hi) {
    u64 d; asm("mov.b64 %0, {%1, %2};" : "=l"(d) : "f"(lo), "f"(hi));
    return d;
}
__device__ __forceinline__ void unpack2(u64 v, float& lo, float& hi) {
    asm("mov.b64 {%0, %1}, %2;" : "=f"(lo), "=f"(hi) : "l"(v));
}

// ---------------------------------------------------------------------------
// Kernel A: P[b,n,k] = sum_h lf[b,n,h]*Wap[h,k] + 0.5*bb[k]
// RA=4 rows/block, 256 threads, 2-way split-K. grid=800 (parallelism fix).
// ---------------------------------------------------------------------------
#define RA 4
__global__ __launch_bounds__(256) void kA(const float* __restrict__ lf,
                                          const float* __restrict__ Wap,
                                          const float* __restrict__ bb) {
    const int r0   = blockIdx.x * RA;
    const int tid  = threadIdx.x;
    const int k    = tid & (HH - 1);
    const int half = tid >> 7;

    __shared__ float row[RA][HH];       // 2 KB
    __shared__ float part[2][RA][HH];   // 4 KB

    {
        const float4* lsrc = (const float4*)(lf + (size_t)r0 * HH);
        for (int t = tid; t < RA * HH / 4; t += 256) ((float4*)row)[t] = lsrc[t];
    }
    __syncthreads();

    float acc[RA];
    const float binit = (half == 0) ? 0.5f * bb[k] : 0.f;
    #pragma unroll
    for (int r = 0; r < RA; ++r) acc[r] = binit;

    const int h0 = half * (HH / 2);
    #pragma unroll 4
    for (int h = h0; h < h0 + HH / 2; ++h) {
        const float wv = Wap[h * HH + k];
        #pragma unroll
        for (int r = 0; r < RA; ++r)
            acc[r] = fmaf(row[r][h], wv, acc[r]);
    }
    #pragma unroll
    for (int r = 0; r < RA; ++r) part[half][r][k] = acc[r];
    __syncthreads();

    for (int t = tid; t < RA * HH; t += 256) {
        const int r = t >> 7, kk = t & (HH - 1);
        d_P[(size_t)(r0 + r) * HH + kk] = part[0][r][kk] + part[1][r][kk];
    }
}

// ---------------------------------------------------------------------------
// Kernel B: block = (b, 4-i tile). 512 threads = 16 warps.
// Warp w: i_local = w>>2, j-quarter q = w&3 (25 consecutive j).
// ALL of P[b] and lf[b] staged in SMEM (kills the per-(b,i) L2 re-stream).
// bin staged pre-duplicated as (v,v) u64 for FFMA2 inner loop.
// Dynamic SMEM: P 51200 + L 51200 + bin_dup 51200 + red 8192 = 161792 B.
// ---------------------------------------------------------------------------
#define TI 4
#define KB_SMEM (51200 + 51200 + 51200 + 8192)

__global__ __launch_bounds__(512, 1) void kB(const float* __restrict__ lf,
                                             const float* __restrict__ bin,
                                             const float* __restrict__ Wb,
                                             const float* __restrict__ Watt,
                                             const float* __restrict__ batt) {
    extern __shared__ char sm[];
    float* P_sh   = (float*)sm;                    // [NN][HH]
    float* L_sh   = (float*)(sm + 51200);          // [NN][HH]
    u64*   bind   = (u64*)(sm + 102400);           // [TI*NN][BIN] dup pairs
    float* red    = (float*)(sm + 153600);         // [TI][4][HH]

    const int blk = blockIdx.x;                    // b*25 + tile
    const int b   = blk / (NN / TI);
    const int i0  = (blk % (NN / TI)) * TI;
    const int tid = threadIdx.x;
    const int w   = tid >> 5;
    const int l   = tid & 31;
    const int k0  = l << 2;
    const int il  = w >> 2;                        // i_local 0..3
    const int q   = w & 3;                         // j-quarter

    // ---- stage P[b], lf[b] (whole batch row-set; L2-resident source) ----
    {
        const float4* Psrc = (const float4*)(d_P + (size_t)b * NN * HH);
        const float4* Lsrc = (const float4*)(lf  + (size_t)b * NN * HH);
        float4* Pd = (float4*)P_sh;
        float4* Ld = (float4*)L_sh;
        for (int t = tid; t < NN * HH / 4; t += 512) { Pd[t] = Psrc[t]; Ld[t] = Lsrc[t]; }
    }
    // ---- stage bin[b, i0..i0+3, :, :] duplicated; streaming loads ----
    {
        const float4* Bsrc = (const float4*)(bin + ((size_t)b * NN + i0) * NN * BIN);
        for (int t = tid; t < TI * NN * BIN / 4; t += 512) {
            const float4 v = __ldcs(Bsrc + t);
            u64* d = &bind[(size_t)(t >> 2) * 4 + ((t & 3) * 4) * 0];   // see below
            // entry (i_local*NN + j) = t>>2 ; c4 = (t&3)*4
            d = &bind[(size_t)(t >> 2) * BIN + ((t & 3) << 2)];
            d[0] = pack2(v.x, v.x);
            d[1] = pack2(v.y, v.y);
            d[2] = pack2(v.z, v.z);
            d[3] = pack2(v.w, v.w);
        }
    }

    // ---- register-resident packed weights ----
    u64 wb01[BIN], wb23[BIN];
    #pragma unroll
    for (int c = 0; c < BIN; ++c) {
        const ulonglong2 v = *(const ulonglong2*)(Wb + c * HH + k0);
        wb01[c] = v.x; wb23[c] = v.y;
    }
    const float4 wa    = *(const float4*)(Watt + k0);
    const float  batt0 = batt[0];

    __syncthreads();

    const ulonglong2 piv = *(const ulonglong2*)(P_sh + (i0 + il) * HH + k0);
    const u64* bd_base   = &bind[(size_t)il * NN * BIN];

    u64 g01 = 0ULL, g23 = 0ULL;

    const int j0 = q * 25;
    #pragma unroll 1
    for (int j = j0; j < j0 + 25; ++j) {
        const ulonglong2 pjv = *(const ulonglong2*)(P_sh + j * HH + k0);
        const ulonglong2 ljv = *(const ulonglong2*)(L_sh + j * HH + k0);

        u64 f01 = add2(piv.x, pjv.x);
        u64 f23 = add2(piv.y, pjv.y);
        const u64* bd = bd_base + (size_t)j * BIN;
        #pragma unroll
        for (int c = 0; c < BIN; ++c) {
            const u64 bc = bd[c];            // LDS.64 broadcast
            f01 = fma2(bc, wb01[c], f01);
            f23 = fma2(bc, wb23[c], f23);
        }

        float f0, f1, f2, f3;
        unpack2(f01, f0, f1);
        unpack2(f23, f2, f3);
        f0 = fmaxf(f0, 0.f); f1 = fmaxf(f1, 0.f);
        f2 = fmaxf(f2, 0.f); f3 = fmaxf(f3, 0.f);

        float part = f0 * wa.x + f1 * wa.y + f2 * wa.z + f3 * wa.w;
        #pragma unroll
        for (int o = 16; o > 0; o >>= 1)
            part += __shfl_xor_sync(0xFFFFFFFFu, part, o);

        const float s  = 1.f / (1.f + __expf(-(part + batt0)));
        const u64   s2 = pack2(s, s);
        g01 = fma2(s2, ljv.x, g01);
        g23 = fma2(s2, ljv.y, g23);
    }

    // ---- reduce the 4 j-quarters per i ----
    {
        float g0, g1, g2, g3;
        unpack2(g01, g0, g1);
        unpack2(g23, g2, g3);
        float4* r4 = (float4*)&red[((il << 2) + q) * HH + k0];
        float4 rv; rv.x = g0; rv.y = g1; rv.z = g2; rv.w = g3;
        *r4 = rv;
    }
    __syncthreads();
    {
        const int ii = tid >> 7;             // 0..3
        const int kk = tid & (HH - 1);
        const float g = (red[((ii << 2) + 0) * HH + kk] + red[((ii << 2) + 1) * HH + kk])
                      + (red[((ii << 2) + 2) * HH + kk] + red[((ii << 2) + 3) * HH + kk]);
        d_G[((size_t)b * NN + i0 + ii) * HH + kk] = g;
    }
}

// ---------------------------------------------------------------------------
// Kernel C: gather epilogue. 2 e per 128-thread block; streaming stores.
// ---------------------------------------------------------------------------
__global__ __launch_bounds__(128) void kC(const float* __restrict__ lf,
                                          const int* __restrict__ idx,
                                          float* __restrict__ out) {
    const int e    = blockIdx.x * 2 + (threadIdx.x >> 6);
    const int half = (threadIdx.x >> 5) & 1;
    const int lane = threadIdx.x & 31;

    int b = idx[e * 3 + 0];
    int i = idx[e * 3 + 1];
    int j = idx[e * 3 + 2];
    b = min(max(b, 0), BB - 1);
    i = min(max(i, 0), NN - 1);
    j = min(max(j, 0), NN - 1);

    const size_t ri = ((size_t)b * NN + i) * (HH / 4);
    const size_t rj = ((size_t)b * NN + j) * (HH / 4);
    float4* o = (float4*)out;

    if (half == 0) {
        const float4* L = (const float4*)lf;
        const float4 a = __ldg(L + ri + lane), c = __ldg(L + rj + lane);
        float4 r; r.x = a.x + c.x; r.y = a.y + c.y; r.z = a.z + c.z; r.w = a.w + c.w;
        __stcs(o + (size_t)e * 32 + lane, r);
    } else {
        const float4* G4 = (const float4*)d_G;
        const float4 a = __ldg(G4 + ri + lane), c = __ldg(G4 + rj + lane);
        float4 r; r.x = a.x + c.x; r.y = a.y + c.y; r.z = a.z + c.z; r.w = a.w + c.w;
        __stcs(o + (size_t)EE * 32 + (size_t)e * 32 + lane, r);
    }
}

// ---------------------------------------------------------------------------
extern "C" void kernel_launch(void* const* d_in, const int* in_sizes, int n_in,
                              void* d_out, int out_size) {
    const float* lf   = (const float*)d_in[0];   // [B,N,H]
    const float* bin  = (const float*)d_in[1];   // [B,N,N,BIN]
    const int*   sidx = (const int*)d_in[2];     // [E,3] int32
    const float* Wap  = (const float*)d_in[3];   // [H,H]
    const float* Wb   = (const float*)d_in[4];   // [BIN,H]
    const float* bb   = (const float*)d_in[5];   // [H]
    const float* Watt = (const float*)d_in[6];   // [H,1]
    const float* batt = (const float*)d_in[7];   // [1]
    float*       out  = (float*)d_out;

    static bool attr_set = false;
    if (!attr_set) {   // idempotent host-side attribute; not a graph node
        cudaFuncSetAttribute(kB, cudaFuncAttributeMaxDynamicSharedMemorySize, KB_SMEM);
        attr_set = true;
    }

    kA<<<BB * NN / RA, 256>>>(lf, Wap, bb);
    kB<<<BB * (NN / TI), 512, KB_SMEM>>>(lf, bin, Wb, Watt, batt);
    kC<<<EE / 2, 128>>>(lf, sidx, out);
}

// round 6
// speedup vs baseline: 1.1501x; 1.0026x over previous
#include <cuda_runtime.h>
#include <math.h>

#define BB   32
#define NN   100
#define HH   128
#define BIN  16
#define EE   20000

// Scratch (allocation-free rule: __device__ globals)
__device__ float d_P[BB * NN * HH];    // P[b,n,k] = lf[b,n]·W_apair[:,k] + 0.5*b_binary[k]
__device__ float d_G[BB * NN * HH];    // global_feats
__device__ float d_ATT[BB * NN * NN];  // att_score[b,i,j]

// ---------------------------------------------------------------------------
// Kernel A: P = lf·Wap + 0.5*bb. 4 rows/block, 4-way split-K, block 512.
// grid 800 -> ~21 warps/SMSP; Wap L2 traffic 51 MB (~5 us floor).
// ---------------------------------------------------------------------------
#define RA 4
__global__ __launch_bounds__(512) void kA(const float* __restrict__ lf,
                                          const float* __restrict__ Wap,
                                          const float* __restrict__ bb) {
    const int r0 = blockIdx.x * RA;
    const int tid = threadIdx.x;
    const int k   = tid & (HH - 1);
    const int q   = tid >> 7;            // 0..3 -> h quarter

    __shared__ float row[RA][HH];        // 2 KB
    __shared__ float part[4][RA][HH];    // 8 KB

    if (tid < RA * HH / 4) {
        const float4* lsrc = (const float4*)(lf + (size_t)r0 * HH);
        ((float4*)row)[tid] = lsrc[tid];
    }
    __syncthreads();

    float acc[RA];
    const float binit = (q == 0) ? 0.5f * bb[k] : 0.f;
    #pragma unroll
    for (int r = 0; r < RA; ++r) acc[r] = binit;

    const int h0 = q * 32;
    #pragma unroll 8
    for (int h = h0; h < h0 + 32; ++h) {
        const float wv = Wap[h * HH + k];
        #pragma unroll
        for (int r = 0; r < RA; ++r)
            acc[r] = fmaf(row[r][h], wv, acc[r]);
    }
    #pragma unroll
    for (int r = 0; r < RA; ++r) part[q][r][k] = acc[r];
    __syncthreads();

    const int r  = tid >> 7;
    const int kk = tid & (HH - 1);
    d_P[(size_t)(r0 + r) * HH + kk] =
        (part[0][r][kk] + part[1][r][kk]) + (part[2][r][kk] + part[3][r][kk]);
}

// ---------------------------------------------------------------------------
// Kernel B1: att_score[b,i,j]. LANE = j (no shuffles, no reductions).
// Block = (b, 10-i tile), 128 threads (4 warps x 32 j-lanes).
// SMEM: Pt[k][j] transposed (stride 105), Wt[k][20] (cols 0-15 = Wb^T, 16 = Wa).
// bin[i,j,:] in 16 registers per lane; 2-i blocking amortizes Wt loads.
// ---------------------------------------------------------------------------
#define TI1 10
#define PT_STRIDE 105
#define WT_STRIDE 20
#define KB1_SMEM (HH * PT_STRIDE * 4 + HH * WT_STRIDE * 4)   // 53760+10240=64000 B

__global__ __launch_bounds__(128) void kB1(const float* __restrict__ bin,
                                           const float* __restrict__ Wb,
                                           const float* __restrict__ Watt,
                                           const float* __restrict__ batt) {
    extern __shared__ float sm1[];
    float* Pt = sm1;                       // [HH][PT_STRIDE]
    float* Wt = sm1 + HH * PT_STRIDE;      // [HH][WT_STRIDE]

    const int b   = blockIdx.x / (NN / TI1);
    const int i0  = (blockIdx.x % (NN / TI1)) * TI1;
    const int tid = threadIdx.x;

    // stage Pt (transposed P[b]) : t -> (j = t>>5, kq = t&31)
    {
        const float4* P4 = (const float4*)(d_P + (size_t)b * NN * HH);
        for (int t = tid; t < NN * (HH / 4); t += 128) {
            const int j  = t >> 5;
            const int kq = t & 31;
            const float4 v = P4[(size_t)j * (HH / 4) + kq];
            Pt[(4 * kq + 0) * PT_STRIDE + j] = v.x;
            Pt[(4 * kq + 1) * PT_STRIDE + j] = v.y;
            Pt[(4 * kq + 2) * PT_STRIDE + j] = v.z;
            Pt[(4 * kq + 3) * PT_STRIDE + j] = v.w;
        }
    }
    // stage Wt: Wt[k][c] = Wb[c][k], Wt[k][16] = Watt[k]
    for (int t = tid; t < BIN * HH; t += 128) {
        const int c = t >> 7, k = t & (HH - 1);
        Wt[k * WT_STRIDE + c] = Wb[c * HH + k];
    }
    if (tid < HH) Wt[tid * WT_STRIDE + 16] = Watt[tid];
    __syncthreads();

    const int  j     = tid;                   // 0..127, valid < 100
    const bool valid = (j < NN);
    const int  jc    = valid ? j : (NN - 1);
    const float batt0 = batt[0];

    #pragma unroll
    for (int ip = 0; ip < TI1; ip += 2) {
        const int iA = i0 + ip, iB = iA + 1;

        // bin regs for both i's (4 x LDG.128 each, high MLP)
        float4 bA0, bA1, bA2, bA3, bB0, bB1, bB2, bB3;
        {
            const float4* pA = (const float4*)(bin + ((size_t)(b * NN + iA) * NN + jc) * BIN);
            const float4* pB = (const float4*)(bin + ((size_t)(b * NN + iB) * NN + jc) * BIN);
            bA0 = __ldg(pA + 0); bA1 = __ldg(pA + 1); bA2 = __ldg(pA + 2); bA3 = __ldg(pA + 3);
            bB0 = __ldg(pB + 0); bB1 = __ldg(pB + 1); bB2 = __ldg(pB + 2); bB3 = __ldg(pB + 3);
        }

        float accA = 0.f, accB = 0.f;
        #pragma unroll 4
        for (int k = 0; k < HH; ++k) {
            const float* wr = &Wt[k * WT_STRIDE];
            const float4 w0 = *(const float4*)(wr + 0);
            const float4 w1 = *(const float4*)(wr + 4);
            const float4 w2 = *(const float4*)(wr + 8);
            const float4 w3 = *(const float4*)(wr + 12);
            const float  wak = wr[16];

            const float pj  = Pt[k * PT_STRIDE + jc];
            float tA = Pt[k * PT_STRIDE + iA] + pj;
            float tB = Pt[k * PT_STRIDE + iB] + pj;

            tA = fmaf(bA0.x, w0.x, tA); tB = fmaf(bB0.x, w0.x, tB);
            tA = fmaf(bA0.y, w0.y, tA); tB = fmaf(bB0.y, w0.y, tB);
            tA = fmaf(bA0.z, w0.z, tA); tB = fmaf(bB0.z, w0.z, tB);
            tA = fmaf(bA0.w, w0.w, tA); tB = fmaf(bB0.w, w0.w, tB);
            tA = fmaf(bA1.x, w1.x, tA); tB = fmaf(bB1.x, w1.x, tB);
            tA = fmaf(bA1.y, w1.y, tA); tB = fmaf(bB1.y, w1.y, tB);
            tA = fmaf(bA1.z, w1.z, tA); tB = fmaf(bB1.z, w1.z, tB);
            tA = fmaf(bA1.w, w1.w, tA); tB = fmaf(bB1.w, w1.w, tB);
            tA = fmaf(bA2.x, w2.x, tA); tB = fmaf(bB2.x, w2.x, tB);
            tA = fmaf(bA2.y, w2.y, tA); tB = fmaf(bB2.y, w2.y, tB);
            tA = fmaf(bA2.z, w2.z, tA); tB = fmaf(bB2.z, w2.z, tB);
            tA = fmaf(bA2.w, w2.w, tA); tB = fmaf(bB2.w, w2.w, tB);
            tA = fmaf(bA3.x, w3.x, tA); tB = fmaf(bB3.x, w3.x, tB);
            tA = fmaf(bA3.y, w3.y, tA); tB = fmaf(bB3.y, w3.y, tB);
            tA = fmaf(bA3.z, w3.z, tA); tB = fmaf(bB3.z, w3.z, tB);
            tA = fmaf(bA3.w, w3.w, tA); tB = fmaf(bB3.w, w3.w, tB);

            tA = fmaxf(tA, 0.f);
            tB = fmaxf(tB, 0.f);
            accA = fmaf(tA, wak, accA);
            accB = fmaf(tB, wak, accB);
        }

        const float sA = 1.f / (1.f + __expf(-(accA + batt0)));
        const float sB = 1.f / (1.f + __expf(-(accB + batt0)));
        if (valid) {
            d_ATT[(size_t)(b * NN + iA) * NN + j] = sA;
            d_ATT[(size_t)(b * NN + iB) * NN + j] = sB;
        }
    }
}

// ---------------------------------------------------------------------------
// Kernel B2: g[b,i,k] = sum_j att[b,i,j] * lf[b,j,k].
// Block = (b, 10-i tile), 128 threads (thread = k). L[b] staged, ii-inner.
// ---------------------------------------------------------------------------
#define KB2_SMEM (NN * HH * 4 + TI1 * NN * 4)   // 51200 + 4000 = 55200 B

__global__ __launch_bounds__(128) void kB2(const float* __restrict__ lf) {
    extern __shared__ float sm2[];
    float* L_sh = sm2;               // [NN][HH]
    float* s_sh = sm2 + NN * HH;     // [TI1][NN]

    const int b   = blockIdx.x / (NN / TI1);
    const int i0  = (blockIdx.x % (NN / TI1)) * TI1;
    const int tid = threadIdx.x;

    {
        const float4* Ls = (const float4*)(lf + (size_t)b * NN * HH);
        float4* Ld = (float4*)L_sh;
        for (int t = tid; t < NN * HH / 4; t += 128) Ld[t] = Ls[t];
        const float* As = d_ATT + (size_t)(b * NN + i0) * NN;
        for (int t = tid; t < TI1 * NN; t += 128) s_sh[t] = As[t];
    }
    __syncthreads();

    const int k = tid;
    float acc[TI1];
    #pragma unroll
    for (int ii = 0; ii < TI1; ++ii) acc[ii] = 0.f;

    #pragma unroll 2
    for (int j = 0; j < NN; ++j) {
        const float lv = L_sh[j * HH + k];
        #pragma unroll
        for (int ii = 0; ii < TI1; ++ii)
            acc[ii] = fmaf(s_sh[ii * NN + j], lv, acc[ii]);
    }
    #pragma unroll
    for (int ii = 0; ii < TI1; ++ii)
        d_G[(size_t)(b * NN + i0 + ii) * HH + k] = acc[ii];
}

// ---------------------------------------------------------------------------
// Kernel C: gather epilogue (float4, streaming stores).
// ---------------------------------------------------------------------------
__global__ __launch_bounds__(128) void kC(const float* __restrict__ lf,
                                          const int* __restrict__ idx,
                                          float* __restrict__ out) {
    const int e    = blockIdx.x * 2 + (threadIdx.x >> 6);
    const int half = (threadIdx.x >> 5) & 1;
    const int lane = threadIdx.x & 31;

    int b = idx[e * 3 + 0];
    int i = idx[e * 3 + 1];
    int j = idx[e * 3 + 2];
    b = min(max(b, 0), BB - 1);
    i = min(max(i, 0), NN - 1);
    j = min(max(j, 0), NN - 1);

    const size_t ri = ((size_t)b * NN + i) * (HH / 4);
    const size_t rj = ((size_t)b * NN + j) * (HH / 4);
    float4* o = (float4*)out;

    if (half == 0) {
        const float4* L = (const float4*)lf;
        const float4 a = __ldg(L + ri + lane), c = __ldg(L + rj + lane);
        float4 r; r.x = a.x + c.x; r.y = a.y + c.y; r.z = a.z + c.z; r.w = a.w + c.w;
        __stcs(o + (size_t)e * 32 + lane, r);
    } else {
        const float4* G4 = (const float4*)d_G;
        const float4 a = __ldg(G4 + ri + lane), c = __ldg(G4 + rj + lane);
        float4 r; r.x = a.x + c.x; r.y = a.y + c.y; r.z = a.z + c.z; r.w = a.w + c.w;
        __stcs(o + (size_t)EE * 32 + (size_t)e * 32 + lane, r);
    }
}

// ---------------------------------------------------------------------------
extern "C" void kernel_launch(void* const* d_in, const int* in_sizes, int n_in,
                              void* d_out, int out_size) {
    const float* lf   = (const float*)d_in[0];
    const float* bin  = (const float*)d_in[1];
    const int*   sidx = (const int*)d_in[2];
    const float* Wap  = (const float*)d_in[3];
    const float* Wb   = (const float*)d_in[4];
    const float* bb   = (const float*)d_in[5];
    const float* Watt = (const float*)d_in[6];
    const float* batt = (const float*)d_in[7];
    float*       out  = (float*)d_out;

    static bool attr_set = false;
    if (!attr_set) {
        cudaFuncSetAttribute(kB1, cudaFuncAttributeMaxDynamicSharedMemorySize, KB1_SMEM);
        cudaFuncSetAttribute(kB2, cudaFuncAttributeMaxDynamicSharedMemorySize, KB2_SMEM);
        attr_set = true;
    }

    kA <<<BB * NN / RA, 512>>>(lf, Wap, bb);
    kB1<<<BB * (NN / TI1), 128, KB1_SMEM>>>(bin, Wb, Watt, batt);
    kB2<<<BB * (NN / TI1), 128, KB2_SMEM>>>(lf);
    kC <<<EE / 2, 128>>>(lf, sidx, out);
}

// round 7
// speedup vs baseline: 1.4113x; 1.2271x over previous
#include <cuda_runtime.h>
#include <math.h>

#define BB   32
#define NN   100
#define HH   128
#define BIN  16
#define EE   20000

typedef unsigned long long u64;

// Scratch (allocation-free rule: __device__ globals)
__device__ float d_P[BB * NN * HH];    // P[b,n,k] = lf[b,n]·W_apair[:,k] + 0.5*b_binary[k]
__device__ float d_G[BB * NN * HH];    // global_feats
__device__ float d_ATT[BB * NN * NN];  // att_score[b,i,j]

// ---- packed f32x2 helpers -------------------------------------------------
__device__ __forceinline__ u64 fma2(u64 a, u64 b, u64 c) {
    u64 d; asm("fma.rn.f32x2 %0, %1, %2, %3;" : "=l"(d) : "l"(a), "l"(b), "l"(c));
    return d;
}
__device__ __forceinline__ u64 add2(u64 a, u64 b) {
    u64 d; asm("add.rn.f32x2 %0, %1, %2;" : "=l"(d) : "l"(a), "l"(b));
    return d;
}
__device__ __forceinline__ u64 pack2(float lo, float hi) {
    u64 d; asm("mov.b64 %0, {%1, %2};" : "=l"(d) : "f"(lo), "f"(hi));
    return d;
}
__device__ __forceinline__ void unpack2(u64 v, float& lo, float& hi) {
    asm("mov.b64 {%0, %1}, %2;" : "=f"(lo), "=f"(hi) : "l"(v));
}

// ---------------------------------------------------------------------------
// Kernel A: P = lf·Wap + 0.5*bb. 4 rows/block, 4-way split-K, block 512.
// ---------------------------------------------------------------------------
#define RA 4
__global__ __launch_bounds__(512) void kA(const float* __restrict__ lf,
                                          const float* __restrict__ Wap,
                                          const float* __restrict__ bb) {
    const int r0 = blockIdx.x * RA;
    const int tid = threadIdx.x;
    const int k   = tid & (HH - 1);
    const int q   = tid >> 7;

    __shared__ float row[RA][HH];
    __shared__ float part[4][RA][HH];

    if (tid < RA * HH / 4) {
        const float4* lsrc = (const float4*)(lf + (size_t)r0 * HH);
        ((float4*)row)[tid] = lsrc[tid];
    }
    __syncthreads();

    float acc[RA];
    const float binit = (q == 0) ? 0.5f * bb[k] : 0.f;
    #pragma unroll
    for (int r = 0; r < RA; ++r) acc[r] = binit;

    const int h0 = q * 32;
    #pragma unroll 8
    for (int h = h0; h < h0 + 32; ++h) {
        const float wv = Wap[h * HH + k];
        #pragma unroll
        for (int r = 0; r < RA; ++r)
            acc[r] = fmaf(row[r][h], wv, acc[r]);
    }
    #pragma unroll
    for (int r = 0; r < RA; ++r) part[q][r][k] = acc[r];
    __syncthreads();

    const int r  = tid >> 7;
    const int kk = tid & (HH - 1);
    d_P[(size_t)(r0 + r) * HH + kk] =
        (part[0][r][kk] + part[1][r][kk]) + (part[2][r][kk] + part[3][r][kk]);
}

// ---------------------------------------------------------------------------
// Kernel B1: att_score[b,i,j]. LANE = j; k packed in f32x2 pairs (FFMA2).
// Block = (b, 4-i tile), 128 threads. Grid 800.
// SMEM: Ptp[kp][j] float2 pairs (k=2kp,2kp+1), Wtp[kp][c] pairs (c16 = Wa).
// bin[i,j,:] duplicated (v,v) in 16 u64 regs per i; 2 i's in flight.
// ---------------------------------------------------------------------------
#define TI1 4
#define PT2_STRIDE 105
#define WT2_STRIDE 18
#define KB1_SMEM (64 * PT2_STRIDE * 8 + 64 * WT2_STRIDE * 8)   // 53760+9216=62976

__global__ __launch_bounds__(128) void kB1(const float* __restrict__ bin,
                                           const float* __restrict__ Wb,
                                           const float* __restrict__ Watt,
                                           const float* __restrict__ batt) {
    extern __shared__ char sm1[];
    float2* Ptp = (float2*)sm1;                            // [64][PT2_STRIDE]
    float2* Wtp = (float2*)(sm1 + 64 * PT2_STRIDE * 8);    // [64][WT2_STRIDE]
    u64*    Ptu = (u64*)Ptp;
    u64*    Wtu = (u64*)Wtp;

    const int b   = blockIdx.x / (NN / TI1);
    const int i0  = (blockIdx.x % (NN / TI1)) * TI1;
    const int tid = threadIdx.x;

    // stage Ptp: pair-along-k transpose of P[b]
    {
        const float4* P4 = (const float4*)(d_P + (size_t)b * NN * HH);
        for (int t = tid; t < NN * (HH / 4); t += 128) {
            const int j  = t >> 5;
            const int kq = t & 31;
            const float4 v = P4[(size_t)j * (HH / 4) + kq];
            Ptp[(2 * kq + 0) * PT2_STRIDE + j] = make_float2(v.x, v.y);
            Ptp[(2 * kq + 1) * PT2_STRIDE + j] = make_float2(v.z, v.w);
        }
    }
    // stage Wtp pairs
    for (int t = tid; t < BIN * 64; t += 128) {
        const int c  = t >> 6;
        const int kp = t & 63;
        Wtp[kp * WT2_STRIDE + c] = make_float2(Wb[c * HH + 2 * kp],
                                               Wb[c * HH + 2 * kp + 1]);
    }
    if (tid < 64)
        Wtp[tid * WT2_STRIDE + 16] = make_float2(Watt[2 * tid], Watt[2 * tid + 1]);
    __syncthreads();

    const int  j     = tid;
    const bool valid = (j < NN);
    const int  jc    = valid ? j : (NN - 1);
    const float batt0 = batt[0];

    #pragma unroll
    for (int ip = 0; ip < TI1; ip += 2) {
        const int iA = i0 + ip, iB = iA + 1;

        // bin regs for both i's, pre-duplicated (v,v)
        u64 dA[BIN], dB[BIN];
        {
            const float4* pA = (const float4*)(bin + ((size_t)(b * NN + iA) * NN + jc) * BIN);
            const float4* pB = (const float4*)(bin + ((size_t)(b * NN + iB) * NN + jc) * BIN);
            #pragma unroll
            for (int q4 = 0; q4 < 4; ++q4) {
                const float4 vA = __ldg(pA + q4);
                const float4 vB = __ldg(pB + q4);
                dA[q4 * 4 + 0] = pack2(vA.x, vA.x);
                dA[q4 * 4 + 1] = pack2(vA.y, vA.y);
                dA[q4 * 4 + 2] = pack2(vA.z, vA.z);
                dA[q4 * 4 + 3] = pack2(vA.w, vA.w);
                dB[q4 * 4 + 0] = pack2(vB.x, vB.x);
                dB[q4 * 4 + 1] = pack2(vB.y, vB.y);
                dB[q4 * 4 + 2] = pack2(vB.z, vB.z);
                dB[q4 * 4 + 3] = pack2(vB.w, vB.w);
            }
        }

        float accAlo = 0.f, accAhi = 0.f, accBlo = 0.f, accBhi = 0.f;

        #pragma unroll 4
        for (int kp = 0; kp < 64; ++kp) {
            const u64* wr  = Wtu + (size_t)kp * WT2_STRIDE;
            const u64  pj2 = Ptu[(size_t)kp * PT2_STRIDE + jc];   // lane-varying LDS.64
            const u64  pA2 = Ptu[(size_t)kp * PT2_STRIDE + iA];   // broadcast
            const u64  pB2 = Ptu[(size_t)kp * PT2_STRIDE + iB];   // broadcast

            u64 tA = add2(pA2, pj2);
            u64 tB = add2(pB2, pj2);
            #pragma unroll
            for (int c = 0; c < BIN; ++c) {
                const u64 w2 = wr[c];                              // broadcast LDS.64
                tA = fma2(dA[c], w2, tA);
                tB = fma2(dB[c], w2, tB);
            }

            float tAlo, tAhi, tBlo, tBhi;
            unpack2(tA, tAlo, tAhi);
            unpack2(tB, tBlo, tBhi);
            tAlo = fmaxf(tAlo, 0.f); tAhi = fmaxf(tAhi, 0.f);      // alu pipe
            tBlo = fmaxf(tBlo, 0.f); tBhi = fmaxf(tBhi, 0.f);

            const float2 wak = ((const float2*)wr)[16];
            accAlo = fmaf(tAlo, wak.x, accAlo);
            accAhi = fmaf(tAhi, wak.y, accAhi);
            accBlo = fmaf(tBlo, wak.x, accBlo);
            accBhi = fmaf(tBhi, wak.y, accBhi);
        }

        const float sA = 1.f / (1.f + __expf(-((accAlo + accAhi) + batt0)));
        const float sB = 1.f / (1.f + __expf(-((accBlo + accBhi) + batt0)));
        if (valid) {
            d_ATT[(size_t)(b * NN + iA) * NN + j] = sA;
            d_ATT[(size_t)(b * NN + iB) * NN + j] = sB;
        }
    }
}

// ---------------------------------------------------------------------------
// Kernel B2: g[b,i,k] = sum_j att[b,i,j] * lf[b,j,k].
// Block = (b, 10-i tile), 128 threads (thread = k). L[b] staged, ii-inner.
// ---------------------------------------------------------------------------
#define TI2 10
#define KB2_SMEM (NN * HH * 4 + TI2 * NN * 4)   // 51200 + 4000 = 55200 B

__global__ __launch_bounds__(128) void kB2(const float* __restrict__ lf) {
    extern __shared__ float sm2[];
    float* L_sh = sm2;               // [NN][HH]
    float* s_sh = sm2 + NN * HH;     // [TI2][NN]

    const int b   = blockIdx.x / (NN / TI2);
    const int i0  = (blockIdx.x % (NN / TI2)) * TI2;
    const int tid = threadIdx.x;

    {
        const float4* Ls = (const float4*)(lf + (size_t)b * NN * HH);
        float4* Ld = (float4*)L_sh;
        for (int t = tid; t < NN * HH / 4; t += 128) Ld[t] = Ls[t];
        const float* As = d_ATT + (size_t)(b * NN + i0) * NN;
        for (int t = tid; t < TI2 * NN; t += 128) s_sh[t] = As[t];
    }
    __syncthreads();

    const int k = tid;
    float acc[TI2];
    #pragma unroll
    for (int ii = 0; ii < TI2; ++ii) acc[ii] = 0.f;

    #pragma unroll 2
    for (int j = 0; j < NN; ++j) {
        const float lv = L_sh[j * HH + k];
        #pragma unroll
        for (int ii = 0; ii < TI2; ++ii)
            acc[ii] = fmaf(s_sh[ii * NN + j], lv, acc[ii]);
    }
    #pragma unroll
    for (int ii = 0; ii < TI2; ++ii)
        d_G[(size_t)(b * NN + i0 + ii) * HH + k] = acc[ii];
}

// ---------------------------------------------------------------------------
// Kernel C: gather epilogue (float4, streaming stores).
// ---------------------------------------------------------------------------
__global__ __launch_bounds__(128) void kC(const float* __restrict__ lf,
                                          const int* __restrict__ idx,
                                          float* __restrict__ out) {
    const int e    = blockIdx.x * 2 + (threadIdx.x >> 6);
    const int half = (threadIdx.x >> 5) & 1;
    const int lane = threadIdx.x & 31;

    int b = idx[e * 3 + 0];
    int i = idx[e * 3 + 1];
    int j = idx[e * 3 + 2];
    b = min(max(b, 0), BB - 1);
    i = min(max(i, 0), NN - 1);
    j = min(max(j, 0), NN - 1);

    const size_t ri = ((size_t)b * NN + i) * (HH / 4);
    const size_t rj = ((size_t)b * NN + j) * (HH / 4);
    float4* o = (float4*)out;

    if (half == 0) {
        const float4* L = (const float4*)lf;
        const float4 a = __ldg(L + ri + lane), c = __ldg(L + rj + lane);
        float4 r; r.x = a.x + c.x; r.y = a.y + c.y; r.z = a.z + c.z; r.w = a.w + c.w;
        __stcs(o + (size_t)e * 32 + lane, r);
    } else {
        const float4* G4 = (const float4*)d_G;
        const float4 a = __ldg(G4 + ri + lane), c = __ldg(G4 + rj + lane);
        float4 r; r.x = a.x + c.x; r.y = a.y + c.y; r.z = a.z + c.z; r.w = a.w + c.w;
        __stcs(o + (size_t)EE * 32 + (size_t)e * 32 + lane, r);
    }
}

// ---------------------------------------------------------------------------
extern "C" void kernel_launch(void* const* d_in, const int* in_sizes, int n_in,
                              void* d_out, int out_size) {
    const float* lf   = (const float*)d_in[0];
    const float* bin  = (const float*)d_in[1];
    const int*   sidx = (const int*)d_in[2];
    const float* Wap  = (const float*)d_in[3];
    const float* Wb   = (const float*)d_in[4];
    const float* bb   = (const float*)d_in[5];
    const float* Watt = (const float*)d_in[6];
    const float* batt = (const float*)d_in[7];
    float*       out  = (float*)d_out;

    static bool attr_set = false;
    if (!attr_set) {
        cudaFuncSetAttribute(kB1, cudaFuncAttributeMaxDynamicSharedMemorySize, KB1_SMEM);
        cudaFuncSetAttribute(kB2, cudaFuncAttributeMaxDynamicSharedMemorySize, KB2_SMEM);
        attr_set = true;
    }

    kA <<<BB * NN / RA, 512>>>(lf, Wap, bb);
    kB1<<<BB * (NN / TI1), 128, KB1_SMEM>>>(bin, Wb, Watt, batt);
    kB2<<<BB * (NN / TI2), 128, KB2_SMEM>>>(lf);
    kC <<<EE / 2, 128>>>(lf, sidx, out);
}

// round 8
// speedup vs baseline: 1.4490x; 1.0267x over previous
#include <cuda_runtime.h>
#include <math.h>
#include <stdint.h>

#define BB   32
#define NN   100
#define HH   128
#define BIN  16
#define EE   20000

// Scratch (allocation-free rule: __device__ globals)
__device__ float d_P[BB * NN * HH];    // P[b,n,k] = lf[b,n]·W_apair[:,k] + 0.5*b_binary[k]
__device__ float d_G[BB * NN * HH];    // global_feats
__device__ float d_ATT[BB * NN * NN];  // att_score[b,i,j]

// ---- tf32 helpers ---------------------------------------------------------
__device__ __forceinline__ uint32_t tf32b(float x) {
    uint32_t r; asm("cvt.rna.tf32.f32 %0, %1;" : "=r"(r) : "f"(x)); return r;
}
// D(16x8) += A(16x8) * B(8x8), tf32 inputs, f32 accum.
__device__ __forceinline__ void mma_tf32(float* d, const uint32_t* a, const uint32_t* bq) {
    asm volatile("mma.sync.aligned.m16n8k8.row.col.f32.tf32.tf32.f32 "
                 "{%0,%1,%2,%3}, {%4,%5,%6,%7}, {%8,%9}, {%0,%1,%2,%3};"
                 : "+f"(d[0]), "+f"(d[1]), "+f"(d[2]), "+f"(d[3])
                 : "r"(a[0]), "r"(a[1]), "r"(a[2]), "r"(a[3]),
                   "r"(bq[0]), "r"(bq[1]));
}

// ---------------------------------------------------------------------------
// Kernel A: P = lf·Wap + 0.5*bb. 4 rows/block, 4-way split-K, block 512.
// ---------------------------------------------------------------------------
#define RA 4
__global__ __launch_bounds__(512) void kA(const float* __restrict__ lf,
                                          const float* __restrict__ Wap,
                                          const float* __restrict__ bb) {
    const int r0 = blockIdx.x * RA;
    const int tid = threadIdx.x;
    const int k   = tid & (HH - 1);
    const int q   = tid >> 7;

    __shared__ float row[RA][HH];
    __shared__ float part[4][RA][HH];

    if (tid < RA * HH / 4) {
        const float4* lsrc = (const float4*)(lf + (size_t)r0 * HH);
        ((float4*)row)[tid] = lsrc[tid];
    }
    __syncthreads();

    float acc[RA];
    const float binit = (q == 0) ? 0.5f * bb[k] : 0.f;
    #pragma unroll
    for (int r = 0; r < RA; ++r) acc[r] = binit;

    const int h0 = q * 32;
    #pragma unroll 8
    for (int h = h0; h < h0 + 32; ++h) {
        const float wv = Wap[h * HH + k];
        #pragma unroll
        for (int r = 0; r < RA; ++r)
            acc[r] = fmaf(row[r][h], wv, acc[r]);
    }
    #pragma unroll
    for (int r = 0; r < RA; ++r) part[q][r][k] = acc[r];
    __syncthreads();

    const int r  = tid >> 7;
    const int kk = tid & (HH - 1);
    d_P[(size_t)(r0 + r) * HH + kk] =
        (part[0][r][kk] + part[1][r][kk]) + (part[2][r][kk] + part[3][r][kk]);
}

// ---------------------------------------------------------------------------
// Kernel B1m: att_score via tf32 mma.sync + fused relu/dot/sigmoid epilogue.
// Block = (b, 4-i tile); warp w owns i = i0+w. M=j (7 tiles of 16, 112 pad),
// N=k (8 chunks of 16), K=c (2 tiles of 8).
// P stays fp32 (epilogue add) — only bin·Wb goes tf32.
// ---------------------------------------------------------------------------
#define TIM 4
#define PS  132   // P_sh row stride (floats); float4-aligned (132*4=528=33*16)
#define BSX 17    // bin_s row stride: banks 17a+b injective -> conflict-free
#define WSX 136   // Wb_s row stride: banks 8b+a injective -> conflict-free
#define KB1M_SMEM (112*PS*4 + TIM*112*BSX*4 + 16*WSX*4 + 128*4)  // 98816 B

__global__ __launch_bounds__(128) void kB1m(const float* __restrict__ bin,
                                            const float* __restrict__ Wb,
                                            const float* __restrict__ Watt,
                                            const float* __restrict__ batt) {
    extern __shared__ float smem[];
    float* P_sh  = smem;                          // [112][PS]
    float* bin_s = smem + 112 * PS;               // [TIM][112][BSX] tf32 bits
    float* Wb_s  = bin_s + TIM * 112 * BSX;       // [16][WSX]       tf32 bits
    float* wa_sh = Wb_s + 16 * WSX;               // [128]

    const int b    = blockIdx.x / (NN / TIM);
    const int i0   = (blockIdx.x % (NN / TIM)) * TIM;
    const int tid  = threadIdx.x;
    const int w    = tid >> 5;
    const int lane = tid & 31;
    const int g    = lane >> 2;   // group id (row sel)
    const int tg   = lane & 3;    // thread in group (col sel)

    // zero bin_s (pad rows 100..111 must be 0)
    for (int t = tid; t < TIM * 112 * BSX; t += 128) bin_s[t] = 0.f;
    __syncthreads();

    // stage P_sh (fp32, stride PS)
    {
        const float4* Ps = (const float4*)(d_P + (size_t)b * NN * HH);
        for (int t = tid; t < NN * 32; t += 128) {
            const int j = t >> 5, kq = t & 31;
            ((float4*)(P_sh + j * PS))[kq] = Ps[t];
        }
    }
    // stage bin_s (tf32-converted), rows 0..99 per i
    for (int t = tid; t < TIM * 400; t += 128) {
        const int ii  = t / 400;
        const int rem = t - ii * 400;
        const int r   = rem >> 2, q = rem & 3;
        const float4 v = __ldg((const float4*)bin +
                               ((size_t)(b * NN + i0 + ii) * NN + r) * 4 + q);
        float* ds = bin_s + (ii * 112 + r) * BSX + 4 * q;
        ds[0] = __uint_as_float(tf32b(v.x));
        ds[1] = __uint_as_float(tf32b(v.y));
        ds[2] = __uint_as_float(tf32b(v.z));
        ds[3] = __uint_as_float(tf32b(v.w));
    }
    // stage Wb_s (tf32)
    for (int t = tid; t < 16 * 32; t += 128) {
        const int c = t >> 5, kq = t & 31;
        const float4 v = ((const float4*)Wb)[t];
        float* ds = Wb_s + c * WSX + 4 * kq;
        ds[0] = __uint_as_float(tf32b(v.x));
        ds[1] = __uint_as_float(tf32b(v.y));
        ds[2] = __uint_as_float(tf32b(v.z));
        ds[3] = __uint_as_float(tf32b(v.w));
    }
    if (tid < HH) wa_sh[tid] = Watt[tid];
    __syncthreads();

    const int i = i0 + w;
    const uint32_t* binU = (const uint32_t*)(bin_s + w * 112 * BSX);
    const uint32_t* WbU  = (const uint32_t*)Wb_s;
    const float batt0 = batt[0];

    float xacc[7][2];
    #pragma unroll
    for (int m = 0; m < 7; ++m) { xacc[m][0] = 0.f; xacc[m][1] = 0.f; }

    #pragma unroll 1
    for (int ch = 0; ch < 8; ++ch) {
        const int nb = ch * 16;

        // B fragments: [Kt][nt][2]
        uint32_t bfr[2][2][2];
        float2 piv[2], wav[2];
        #pragma unroll
        for (int nt = 0; nt < 2; ++nt) {
            const int kf = nb + nt * 8 + g;
            bfr[0][nt][0] = WbU[(tg)      * WSX + kf];
            bfr[0][nt][1] = WbU[(tg + 4)  * WSX + kf];
            bfr[1][nt][0] = WbU[(tg + 8)  * WSX + kf];
            bfr[1][nt][1] = WbU[(tg + 12) * WSX + kf];
            const int k0 = nb + nt * 8 + 2 * tg;
            piv[nt] = *(const float2*)(P_sh + i * PS + k0);   // broadcast-ish
            wav[nt] = *(const float2*)(wa_sh + k0);
        }

        #pragma unroll
        for (int Mt = 0; Mt < 7; ++Mt) {
            const int r0 = Mt * 16 + g;
            uint32_t a0[4], a1[4];
            a0[0] = binU[(r0)     * BSX + tg];
            a0[1] = binU[(r0 + 8) * BSX + tg];
            a0[2] = binU[(r0)     * BSX + tg + 4];
            a0[3] = binU[(r0 + 8) * BSX + tg + 4];
            a1[0] = binU[(r0)     * BSX + tg + 8];
            a1[1] = binU[(r0 + 8) * BSX + tg + 8];
            a1[2] = binU[(r0)     * BSX + tg + 12];
            a1[3] = binU[(r0 + 8) * BSX + tg + 12];

            float acc[2][4] = {{0.f,0.f,0.f,0.f},{0.f,0.f,0.f,0.f}};
            mma_tf32(acc[0], a0, bfr[0][0]);
            mma_tf32(acc[0], a1, bfr[1][0]);
            mma_tf32(acc[1], a0, bfr[0][1]);
            mma_tf32(acc[1], a1, bfr[1][1]);

            #pragma unroll
            for (int nt = 0; nt < 2; ++nt) {
                const int k0 = nb + nt * 8 + 2 * tg;
                const float2 pj0 = *(const float2*)(P_sh + (r0)     * PS + k0);
                const float2 pj1 = *(const float2*)(P_sh + (r0 + 8) * PS + k0);
                float f;
                f = fmaxf(acc[nt][0] + piv[nt].x + pj0.x, 0.f);
                xacc[Mt][0] = fmaf(f, wav[nt].x, xacc[Mt][0]);
                f = fmaxf(acc[nt][1] + piv[nt].y + pj0.y, 0.f);
                xacc[Mt][0] = fmaf(f, wav[nt].y, xacc[Mt][0]);
                f = fmaxf(acc[nt][2] + piv[nt].x + pj1.x, 0.f);
                xacc[Mt][1] = fmaf(f, wav[nt].x, xacc[Mt][1]);
                f = fmaxf(acc[nt][3] + piv[nt].y + pj1.y, 0.f);
                xacc[Mt][1] = fmaf(f, wav[nt].y, xacc[Mt][1]);
            }
        }
    }

    // quad-reduce rows, sigmoid, store
    #pragma unroll
    for (int Mt = 0; Mt < 7; ++Mt) {
        #pragma unroll
        for (int rh = 0; rh < 2; ++rh) {
            float x = xacc[Mt][rh];
            x += __shfl_xor_sync(0xFFFFFFFFu, x, 1);
            x += __shfl_xor_sync(0xFFFFFFFFu, x, 2);
            const int j = Mt * 16 + g + 8 * rh;
            if (tg == 0 && j < NN) {
                const float s = 1.f / (1.f + __expf(-(x + batt0)));
                d_ATT[(size_t)(b * NN + i) * NN + j] = s;
            }
        }
    }
}

// ---------------------------------------------------------------------------
// Kernel B2: g[b,i,k] = sum_j att[b,i,j] * lf[b,j,k].
// ---------------------------------------------------------------------------
#define TI2 10
#define KB2_SMEM (NN * HH * 4 + TI2 * NN * 4)   // 55200 B

__global__ __launch_bounds__(128) void kB2(const float* __restrict__ lf) {
    extern __shared__ float sm2[];
    float* L_sh = sm2;               // [NN][HH]
    float* s_sh = sm2 + NN * HH;     // [TI2][NN]

    const int b   = blockIdx.x / (NN / TI2);
    const int i0  = (blockIdx.x % (NN / TI2)) * TI2;
    const int tid = threadIdx.x;

    {
        const float4* Ls = (const float4*)(lf + (size_t)b * NN * HH);
        float4* Ld = (float4*)L_sh;
        for (int t = tid; t < NN * HH / 4; t += 128) Ld[t] = Ls[t];
        const float* As = d_ATT + (size_t)(b * NN + i0) * NN;
        for (int t = tid; t < TI2 * NN; t += 128) s_sh[t] = As[t];
    }
    __syncthreads();

    const int k = tid;
    float acc[TI2];
    #pragma unroll
    for (int ii = 0; ii < TI2; ++ii) acc[ii] = 0.f;

    #pragma unroll 2
    for (int j = 0; j < NN; ++j) {
        const float lv = L_sh[j * HH + k];
        #pragma unroll
        for (int ii = 0; ii < TI2; ++ii)
            acc[ii] = fmaf(s_sh[ii * NN + j], lv, acc[ii]);
    }
    #pragma unroll
    for (int ii = 0; ii < TI2; ++ii)
        d_G[(size_t)(b * NN + i0 + ii) * HH + k] = acc[ii];
}

// ---------------------------------------------------------------------------
// Kernel C: gather epilogue (float4, streaming stores).
// ---------------------------------------------------------------------------
__global__ __launch_bounds__(128) void kC(const float* __restrict__ lf,
                                          const int* __restrict__ idx,
                                          float* __restrict__ out) {
    const int e    = blockIdx.x * 2 + (threadIdx.x >> 6);
    const int half = (threadIdx.x >> 5) & 1;
    const int lane = threadIdx.x & 31;

    int b = idx[e * 3 + 0];
    int i = idx[e * 3 + 1];
    int j = idx[e * 3 + 2];
    b = min(max(b, 0), BB - 1);
    i = min(max(i, 0), NN - 1);
    j = min(max(j, 0), NN - 1);

    const size_t ri = ((size_t)b * NN + i) * (HH / 4);
    const size_t rj = ((size_t)b * NN + j) * (HH / 4);
    float4* o = (float4*)out;

    if (half == 0) {
        const float4* L = (const float4*)lf;
        const float4 a = __ldg(L + ri + lane), c = __ldg(L + rj + lane);
        float4 r; r.x = a.x + c.x; r.y = a.y + c.y; r.z = a.z + c.z; r.w = a.w + c.w;
        __stcs(o + (size_t)e * 32 + lane, r);
    } else {
        const float4* G4 = (const float4*)d_G;
        const float4 a = __ldg(G4 + ri + lane), c = __ldg(G4 + rj + lane);
        float4 r; r.x = a.x + c.x; r.y = a.y + c.y; r.z = a.z + c.z; r.w = a.w + c.w;
        __stcs(o + (size_t)EE * 32 + (size_t)e * 32 + lane, r);
    }
}

// ---------------------------------------------------------------------------
extern "C" void kernel_launch(void* const* d_in, const int* in_sizes, int n_in,
                              void* d_out, int out_size) {
    const float* lf   = (const float*)d_in[0];
    const float* bin  = (const float*)d_in[1];
    const int*   sidx = (const int*)d_in[2];
    const float* Wap  = (const float*)d_in[3];
    const float* Wb   = (const float*)d_in[4];
    const float* bb   = (const float*)d_in[5];
    const float* Watt = (const float*)d_in[6];
    const float* batt = (const float*)d_in[7];
    float*       out  = (float*)d_out;

    static bool attr_set = false;
    if (!attr_set) {
        cudaFuncSetAttribute(kB1m, cudaFuncAttributeMaxDynamicSharedMemorySize, KB1M_SMEM);
        cudaFuncSetAttribute(kB2,  cudaFuncAttributeMaxDynamicSharedMemorySize, KB2_SMEM);
        attr_set = true;
    }

    kA  <<<BB * NN / RA, 512>>>(lf, Wap, bb);
    kB1m<<<BB * (NN / TIM), 128, KB1M_SMEM>>>(bin, Wb, Watt, batt);
    kB2 <<<BB * (NN / TI2), 128, KB2_SMEM>>>(lf);
    kC  <<<EE / 2, 128>>>(lf, sidx, out);
}

// round 10
// speedup vs baseline: 1.6187x; 1.1171x over previous
#include <cuda_runtime.h>
#include <math.h>
#include <stdint.h>

#define BB   32
#define NN   100
#define HH   128
#define BIN  16
#define EE   20000

// Scratch (allocation-free rule: __device__ globals)
__device__ float d_P[BB * NN * HH];    // P[b,n,k] = lf[b,n]·W_apair[:,k] + 0.5*b_binary[k]
__device__ float d_G[BB * NN * HH];    // global_feats
__device__ float d_ATT[BB * NN * NN];  // att_score[b,i,j]

// ---- tf32 helpers ---------------------------------------------------------
__device__ __forceinline__ uint32_t tf32b(float x) {
    uint32_t r; asm("cvt.rna.tf32.f32 %0, %1;" : "=r"(r) : "f"(x)); return r;
}
__device__ __forceinline__ void mma_tf32(float* d, const uint32_t* a, const uint32_t* bq) {
    asm volatile("mma.sync.aligned.m16n8k8.row.col.f32.tf32.tf32.f32 "
                 "{%0,%1,%2,%3}, {%4,%5,%6,%7}, {%8,%9}, {%0,%1,%2,%3};"
                 : "+f"(d[0]), "+f"(d[1]), "+f"(d[2]), "+f"(d[3])
                 : "r"(a[0]), "r"(a[1]), "r"(a[2]), "r"(a[3]),
                   "r"(bq[0]), "r"(bq[1]));
}

// ---------------------------------------------------------------------------
// Kernel A: P = lf·Wap + 0.5*bb. RA=8 rows/block, 4-way split-K, block 512.
// grid 400; Wap L2 traffic 26 MB.
// ---------------------------------------------------------------------------
#define RA 8
__global__ __launch_bounds__(512) void kA(const float* __restrict__ lf,
                                          const float* __restrict__ Wap,
                                          const float* __restrict__ bb) {
    const int r0  = blockIdx.x * RA;
    const int tid = threadIdx.x;
    const int k   = tid & (HH - 1);
    const int q   = tid >> 7;

    __shared__ float row[RA][HH];        // 4 KB
    __shared__ float part[4][RA][HH];    // 16 KB

    if (tid < RA * HH / 4) {
        const float4* lsrc = (const float4*)(lf + (size_t)r0 * HH);
        ((float4*)row)[tid] = lsrc[tid];
    }
    __syncthreads();

    float acc[RA];
    const float binit = (q == 0) ? 0.5f * bb[k] : 0.f;
    #pragma unroll
    for (int r = 0; r < RA; ++r) acc[r] = binit;

    const int h0 = q * 32;
    #pragma unroll 8
    for (int h = h0; h < h0 + 32; ++h) {
        const float wv = Wap[h * HH + k];
        #pragma unroll
        for (int r = 0; r < RA; ++r)
            acc[r] = fmaf(row[r][h], wv, acc[r]);
    }
    #pragma unroll
    for (int r = 0; r < RA; ++r) part[q][r][k] = acc[r];
    __syncthreads();

    for (int t = tid; t < RA * HH; t += 512) {
        const int r = t >> 7, kk = t & (HH - 1);
        d_P[(size_t)(r0 + r) * HH + kk] =
            (part[0][r][kk] + part[1][r][kk]) + (part[2][r][kk] + part[3][r][kk]);
    }
}

// ---------------------------------------------------------------------------
// Kernel B1m: att_score via tf32 mma.sync.
// Block = (b, 4-i tile), 512 threads = 16 warps: warp = (i_local, k-quarter).
// Each warp runs 2 of the 8 k-chunks (ch = 2*kq, 2*kq+1).
// Accumulator initialized with P_i + P_j fragment values (D += A·B).
// k-quarter partials combined through SMEM red + fused sigmoid pass.
// ---------------------------------------------------------------------------
#define TIM 4
#define PS  132   // P_sh row stride
#define BSX 17    // bin_s row stride (conflict-free for A-frag pattern)
#define WSX 136   // Wb_s row stride (conflict-free for B-frag pattern)
// P_sh 112*132*4 + bin_s 4*112*17*4 + Wb_s 16*136*4 + wa 512 + red 4*4*112*4
#define KB1M_SMEM (59136 + 30464 + 8704 + 512 + 7168)   // 105984 B

__global__ __launch_bounds__(512) void kB1m(const float* __restrict__ bin,
                                            const float* __restrict__ Wb,
                                            const float* __restrict__ Watt,
                                            const float* __restrict__ batt) {
    extern __shared__ float smem[];
    float* P_sh  = smem;                          // [112][PS]
    float* bin_s = smem + 112 * PS;               // [TIM][112][BSX] tf32 bits
    float* Wb_s  = bin_s + TIM * 112 * BSX;       // [16][WSX]       tf32 bits
    float* wa_sh = Wb_s + 16 * WSX;               // [128]
    float* red   = wa_sh + 128;                   // [TIM][4][112]

    const int b    = blockIdx.x / (NN / TIM);
    const int i0   = (blockIdx.x % (NN / TIM)) * TIM;
    const int tid  = threadIdx.x;
    const int w    = tid >> 5;
    const int lane = tid & 31;
    const int g    = lane >> 2;   // 0..7 (row sel)
    const int tg   = lane & 3;    // 0..3 (col sel)
    const int il   = w >> 2;      // i_local
    const int kq   = w & 3;       // k-quarter

    // zero ONLY pad rows (100..111) of bin_s and P_sh
    for (int t = tid; t < TIM * 12 * BSX; t += 512) {
        const int ii = t / (12 * BSX);
        bin_s[(ii * 112 + 100) * BSX + (t - ii * 12 * BSX)] = 0.f;
    }
    for (int t = tid; t < 12 * PS; t += 512) P_sh[100 * PS + t] = 0.f;

    // stage P_sh rows 0..99 (fp32)
    {
        const float4* Ps = (const float4*)(d_P + (size_t)b * NN * HH);
        for (int t = tid; t < NN * 32; t += 512) {
            const int j = t >> 5, kqq = t & 31;
            ((float4*)(P_sh + j * PS))[kqq] = Ps[t];
        }
    }
    // stage bin_s (tf32)
    for (int t = tid; t < TIM * 400; t += 512) {
        const int ii  = t / 400;
        const int rem = t - ii * 400;
        const int r   = rem >> 2, q = rem & 3;
        const float4 v = __ldg((const float4*)bin +
                               ((size_t)(b * NN + i0 + ii) * NN + r) * 4 + q);
        float* ds = bin_s + (ii * 112 + r) * BSX + 4 * q;
        ds[0] = __uint_as_float(tf32b(v.x));
        ds[1] = __uint_as_float(tf32b(v.y));
        ds[2] = __uint_as_float(tf32b(v.z));
        ds[3] = __uint_as_float(tf32b(v.w));
    }
    // stage Wb_s (tf32): one element per thread
    if (tid < 16 * 32) {
        const int c = tid >> 5, kqq = tid & 31;
        const float4 v = ((const float4*)Wb)[tid];
        float* ds = Wb_s + c * WSX + 4 * kqq;
        ds[0] = __uint_as_float(tf32b(v.x));
        ds[1] = __uint_as_float(tf32b(v.y));
        ds[2] = __uint_as_float(tf32b(v.z));
        ds[3] = __uint_as_float(tf32b(v.w));
    }
    if (tid < HH) wa_sh[tid] = Watt[tid];
    __syncthreads();

    const int i = i0 + il;
    const uint32_t* binU = (const uint32_t*)(bin_s + il * 112 * BSX);
    const uint32_t* WbU  = (const uint32_t*)Wb_s;

    float xacc[7][2];
    #pragma unroll
    for (int m = 0; m < 7; ++m) { xacc[m][0] = 0.f; xacc[m][1] = 0.f; }

    #pragma unroll
    for (int cc = 0; cc < 2; ++cc) {
        const int ch = kq * 2 + cc;
        const int nb = ch * 16;

        uint32_t bfr[2][2][2];
        float2 piv[2], wav[2];
        #pragma unroll
        for (int nt = 0; nt < 2; ++nt) {
            const int kf = nb + nt * 8 + g;
            bfr[0][nt][0] = WbU[(tg)      * WSX + kf];
            bfr[0][nt][1] = WbU[(tg + 4)  * WSX + kf];
            bfr[1][nt][0] = WbU[(tg + 8)  * WSX + kf];
            bfr[1][nt][1] = WbU[(tg + 12) * WSX + kf];
            const int k0 = nb + nt * 8 + 2 * tg;
            piv[nt] = *(const float2*)(P_sh + i * PS + k0);
            wav[nt] = *(const float2*)(wa_sh + k0);
        }

        #pragma unroll
        for (int Mt = 0; Mt < 7; ++Mt) {
            const int r0 = Mt * 16 + g;
            uint32_t a0[4], a1[4];
            a0[0] = binU[(r0)     * BSX + tg];
            a0[1] = binU[(r0 + 8) * BSX + tg];
            a0[2] = binU[(r0)     * BSX + tg + 4];
            a0[3] = binU[(r0 + 8) * BSX + tg + 4];
            a1[0] = binU[(r0)     * BSX + tg + 8];
            a1[1] = binU[(r0 + 8) * BSX + tg + 8];
            a1[2] = binU[(r0)     * BSX + tg + 12];
            a1[3] = binU[(r0 + 8) * BSX + tg + 12];

            // acc initialized with P_i + P_j at fragment positions
            float acc[2][4];
            #pragma unroll
            for (int nt = 0; nt < 2; ++nt) {
                const int k0 = nb + nt * 8 + 2 * tg;
                const float2 pj0 = *(const float2*)(P_sh + (r0)     * PS + k0);
                const float2 pj1 = *(const float2*)(P_sh + (r0 + 8) * PS + k0);
                acc[nt][0] = piv[nt].x + pj0.x;
                acc[nt][1] = piv[nt].y + pj0.y;
                acc[nt][2] = piv[nt].x + pj1.x;
                acc[nt][3] = piv[nt].y + pj1.y;
            }

            mma_tf32(acc[0], a0, bfr[0][0]);
            mma_tf32(acc[0], a1, bfr[1][0]);
            mma_tf32(acc[1], a0, bfr[0][1]);
            mma_tf32(acc[1], a1, bfr[1][1]);

            #pragma unroll
            for (int nt = 0; nt < 2; ++nt) {
                float f;
                f = fmaxf(acc[nt][0], 0.f);
                xacc[Mt][0] = fmaf(f, wav[nt].x, xacc[Mt][0]);
                f = fmaxf(acc[nt][1], 0.f);
                xacc[Mt][0] = fmaf(f, wav[nt].y, xacc[Mt][0]);
                f = fmaxf(acc[nt][2], 0.f);
                xacc[Mt][1] = fmaf(f, wav[nt].x, xacc[Mt][1]);
                f = fmaxf(acc[nt][3], 0.f);
                xacc[Mt][1] = fmaf(f, wav[nt].y, xacc[Mt][1]);
            }
        }
    }

    // quad-reduce rows, stash k-quarter partials
    #pragma unroll
    for (int Mt = 0; Mt < 7; ++Mt) {
        #pragma unroll
        for (int rh = 0; rh < 2; ++rh) {
            float x = xacc[Mt][rh];
            x += __shfl_xor_sync(0xFFFFFFFFu, x, 1);
            x += __shfl_xor_sync(0xFFFFFFFFu, x, 2);
            if (tg == 0)
                red[(il * 4 + kq) * 112 + Mt * 16 + g + 8 * rh] = x;
        }
    }
    __syncthreads();

    // combine k-quarters + sigmoid + store
    if (tid < TIM * 112) {
        const int ii = tid / 112;
        const int j  = tid - ii * 112;
        if (j < NN) {
            const float* r4 = red + ii * 4 * 112 + j;
            const float x = (r4[0] + r4[112]) + (r4[224] + r4[336]);
            const float s = 1.f / (1.f + __expf(-(x + batt[0])));
            d_ATT[(size_t)(b * NN + i0 + ii) * NN + j] = s;
        }
    }
}

// ---------------------------------------------------------------------------
// Kernel B2: g[b,i,k] = sum_j att[b,i,j] * lf[b,j,k].
// ---------------------------------------------------------------------------
#define TI2 10
#define KB2_SMEM (NN * HH * 4 + TI2 * NN * 4)   // 55200 B

__global__ __launch_bounds__(128) void kB2(const float* __restrict__ lf) {
    extern __shared__ float sm2[];
    float* L_sh = sm2;               // [NN][HH]
    float* s_sh = sm2 + NN * HH;     // [TI2][NN]

    const int b   = blockIdx.x / (NN / TI2);
    const int i0  = (blockIdx.x % (NN / TI2)) * TI2;
    const int tid = threadIdx.x;

    {
        const float4* Ls = (const float4*)(lf + (size_t)b * NN * HH);
        float4* Ld = (float4*)L_sh;
        for (int t = tid; t < NN * HH / 4; t += 128) Ld[t] = Ls[t];
        const float* As = d_ATT + (size_t)(b * NN + i0) * NN;
        for (int t = tid; t < TI2 * NN; t += 128) s_sh[t] = As[t];
    }
    __syncthreads();

    const int k = tid;
    float acc[TI2];
    #pragma unroll
    for (int ii = 0; ii < TI2; ++ii) acc[ii] = 0.f;

    #pragma unroll 2
    for (int j = 0; j < NN; ++j) {
        const float lv = L_sh[j * HH + k];
        #pragma unroll
        for (int ii = 0; ii < TI2; ++ii)
            acc[ii] = fmaf(s_sh[ii * NN + j], lv, acc[ii]);
    }
    #pragma unroll
    for (int ii = 0; ii < TI2; ++ii)
        d_G[(size_t)(b * NN + i0 + ii) * HH + k] = acc[ii];
}

// ---------------------------------------------------------------------------
// Kernel C: gather epilogue (float4, streaming stores).
// ---------------------------------------------------------------------------
__global__ __launch_bounds__(128) void kC(const float* __restrict__ lf,
                                          const int* __restrict__ idx,
                                          float* __restrict__ out) {
    const int e    = blockIdx.x * 2 + (threadIdx.x >> 6);
    const int half = (threadIdx.x >> 5) & 1;
    const int lane = threadIdx.x & 31;

    int b = idx[e * 3 + 0];
    int i = idx[e * 3 + 1];
    int j = idx[e * 3 + 2];
    b = min(max(b, 0), BB - 1);
    i = min(max(i, 0), NN - 1);
    j = min(max(j, 0), NN - 1);

    const size_t ri = ((size_t)b * NN + i) * (HH / 4);
    const size_t rj = ((size_t)b * NN + j) * (HH / 4);
    float4* o = (float4*)out;

    if (half == 0) {
        const float4* L = (const float4*)lf;
        const float4 a = __ldg(L + ri + lane), c = __ldg(L + rj + lane);
        float4 r; r.x = a.x + c.x; r.y = a.y + c.y; r.z = a.z + c.z; r.w = a.w + c.w;
        __stcs(o + (size_t)e * 32 + lane, r);
    } else {
        const float4* G4 = (const float4*)d_G;
        const float4 a = __ldg(G4 + ri + lane), c = __ldg(G4 + rj + lane);
        float4 r; r.x = a.x + c.x; r.y = a.y + c.y; r.z = a.z + c.z; r.w = a.w + c.w;
        __stcs(o + (size_t)EE * 32 + (size_t)e * 32 + lane, r);
    }
}

// ---------------------------------------------------------------------------
extern "C" void kernel_launch(void* const* d_in, const int* in_sizes, int n_in,
                              void* d_out, int out_size) {
    const float* lf   = (const float*)d_in[0];
    const float* bin  = (const float*)d_in[1];
    const int*   sidx = (const int*)d_in[2];
    const float* Wap  = (const float*)d_in[3];
    const float* Wb   = (const float*)d_in[4];
    const float* bb   = (const float*)d_in[5];
    const float* Watt = (const float*)d_in[6];
    const float* batt = (const float*)d_in[7];
    float*       out  = (float*)d_out;

    static bool attr_set = false;
    if (!attr_set) {
        cudaFuncSetAttribute(kB1m, cudaFuncAttributeMaxDynamicSharedMemorySize, KB1M_SMEM);
        cudaFuncSetAttribute(kB2,  cudaFuncAttributeMaxDynamicSharedMemorySize, KB2_SMEM);
        attr_set = true;
    }

    kA  <<<BB * NN / RA, 512>>>(lf, Wap, bb);
    kB1m<<<BB * (NN / TIM), 512, KB1M_SMEM>>>(bin, Wb, Watt, batt);
    kB2 <<<BB * (NN / TI2), 128, KB2_SMEM>>>(lf);
    kC  <<<EE / 2, 128>>>(lf, sidx, out);
}

// round 11
// speedup vs baseline: 1.8987x; 1.1730x over previous
#include <cuda_runtime.h>
#include <math.h>
#include <stdint.h>

#define BB   32
#define NN   100
#define HH   128
#define BIN  16
#define EE   20000

// Scratch (allocation-free rule: __device__ globals)
__device__ float d_P[BB * NN * HH];    // P[b,n,k] = lf[b,n]·W_apair[:,k] + 0.5*b_binary[k]
__device__ float d_G[BB * NN * HH];    // global_feats
__device__ float d_ATT[BB * NN * NN];  // att_score[b,i,j]

// ---- tf32 helpers ---------------------------------------------------------
__device__ __forceinline__ uint32_t tf32b(float x) {
    uint32_t r; asm("cvt.rna.tf32.f32 %0, %1;" : "=r"(r) : "f"(x)); return r;
}
__device__ __forceinline__ void mma_tf32(float* d, const uint32_t* a, const uint32_t* bq) {
    asm volatile("mma.sync.aligned.m16n8k8.row.col.f32.tf32.tf32.f32 "
                 "{%0,%1,%2,%3}, {%4,%5,%6,%7}, {%8,%9}, {%0,%1,%2,%3};"
                 : "+f"(d[0]), "+f"(d[1]), "+f"(d[2]), "+f"(d[3])
                 : "r"(a[0]), "r"(a[1]), "r"(a[2]), "r"(a[3]),
                   "r"(bq[0]), "r"(bq[1]));
}

// ---------------------------------------------------------------------------
// Kernel A: P = lf·Wap + 0.5*bb. RA=8 rows/block, 4-way split-K, block 512.
// ---------------------------------------------------------------------------
#define RA 8
__global__ __launch_bounds__(512) void kA(const float* __restrict__ lf,
                                          const float* __restrict__ Wap,
                                          const float* __restrict__ bb) {
    const int r0  = blockIdx.x * RA;
    const int tid = threadIdx.x;
    const int k   = tid & (HH - 1);
    const int q   = tid >> 7;

    __shared__ float row[RA][HH];
    __shared__ float part[4][RA][HH];

    if (tid < RA * HH / 4) {
        const float4* lsrc = (const float4*)(lf + (size_t)r0 * HH);
        ((float4*)row)[tid] = lsrc[tid];
    }
    __syncthreads();

    float acc[RA];
    const float binit = (q == 0) ? 0.5f * bb[k] : 0.f;
    #pragma unroll
    for (int r = 0; r < RA; ++r) acc[r] = binit;

    const int h0 = q * 32;
    #pragma unroll 8
    for (int h = h0; h < h0 + 32; ++h) {
        const float wv = Wap[h * HH + k];
        #pragma unroll
        for (int r = 0; r < RA; ++r)
            acc[r] = fmaf(row[r][h], wv, acc[r]);
    }
    #pragma unroll
    for (int r = 0; r < RA; ++r) part[q][r][k] = acc[r];
    __syncthreads();

    for (int t = tid; t < RA * HH; t += 512) {
        const int r = t >> 7, kk = t & (HH - 1);
        d_P[(size_t)(r0 + r) * HH + kk] =
            (part[0][r][kk] + part[1][r][kk]) + (part[2][r][kk] + part[3][r][kk]);
    }
}

// ---------------------------------------------------------------------------
// Kernel B1m: att_score via tf32 mma.sync. Mt-outer restructure.
// Block = (b, 4-i tile), 512 threads = 16 warps: warp = (i_local, k-quarter).
// __launch_bounds__(512,2): <=64 regs, guaranteed 2 CTAs/SM (32 warps/SM).
// A-fragments loaded ONCE per Mt (shared by both k-chunks).
// bin_s stride 20: conflict-free A-frag LDS (20g mod 32 disjoint 4-blocks).
// ---------------------------------------------------------------------------
#define TIM 4
#define PS  132   // P_sh row stride (2-way on epilogue float2, accepted)
#define BSX 20    // bin_s row stride: conflict-free for A-frag pattern
#define WSX 136   // Wb_s row stride: conflict-free for B-frag pattern
// P_sh 59136 + bin_s 4*112*20*4=35840 + Wb_s 8704 + wa 512 + red 7168
#define KB1M_SMEM (59136 + 35840 + 8704 + 512 + 7168)   // 111360 B

__global__ __launch_bounds__(512, 2) void kB1m(const float* __restrict__ bin,
                                               const float* __restrict__ Wb,
                                               const float* __restrict__ Watt,
                                               const float* __restrict__ batt) {
    extern __shared__ float smem[];
    float* P_sh  = smem;                          // [112][PS]
    float* bin_s = smem + 112 * PS;               // [TIM][112][BSX] tf32 bits
    float* Wb_s  = bin_s + TIM * 112 * BSX;       // [16][WSX]       tf32 bits
    float* wa_sh = Wb_s + 16 * WSX;               // [128]
    float* red   = wa_sh + 128;                   // [TIM][4][112]

    const int b    = blockIdx.x / (NN / TIM);
    const int i0   = (blockIdx.x % (NN / TIM)) * TIM;
    const int tid  = threadIdx.x;
    const int w    = tid >> 5;
    const int lane = tid & 31;
    const int g    = lane >> 2;   // 0..7 (row sel)
    const int tg   = lane & 3;    // 0..3 (col sel)
    const int il   = w >> 2;      // i_local
    const int kq   = w & 3;       // k-quarter

    // zero ONLY pad rows (100..111) of bin_s and P_sh
    for (int t = tid; t < TIM * 12 * BSX; t += 512) {
        const int ii = t / (12 * BSX);
        bin_s[(ii * 112 + 100) * BSX + (t - ii * 12 * BSX)] = 0.f;
    }
    for (int t = tid; t < 12 * PS; t += 512) P_sh[100 * PS + t] = 0.f;

    // stage P_sh rows 0..99 (fp32)
    {
        const float4* Ps = (const float4*)(d_P + (size_t)b * NN * HH);
        for (int t = tid; t < NN * 32; t += 512) {
            const int j = t >> 5, kqq = t & 31;
            ((float4*)(P_sh + j * PS))[kqq] = Ps[t];
        }
    }
    // stage bin_s (tf32)
    for (int t = tid; t < TIM * 400; t += 512) {
        const int ii  = t / 400;
        const int rem = t - ii * 400;
        const int r   = rem >> 2, q = rem & 3;
        const float4 v = __ldg((const float4*)bin +
                               ((size_t)(b * NN + i0 + ii) * NN + r) * 4 + q);
        float* ds = bin_s + (ii * 112 + r) * BSX + 4 * q;
        ds[0] = __uint_as_float(tf32b(v.x));
        ds[1] = __uint_as_float(tf32b(v.y));
        ds[2] = __uint_as_float(tf32b(v.z));
        ds[3] = __uint_as_float(tf32b(v.w));
    }
    // stage Wb_s (tf32)
    if (tid < 16 * 32) {
        const int c = tid >> 5, kqq = tid & 31;
        const float4 v = ((const float4*)Wb)[tid];
        float* ds = Wb_s + c * WSX + 4 * kqq;
        ds[0] = __uint_as_float(tf32b(v.x));
        ds[1] = __uint_as_float(tf32b(v.y));
        ds[2] = __uint_as_float(tf32b(v.z));
        ds[3] = __uint_as_float(tf32b(v.w));
    }
    if (tid < HH) wa_sh[tid] = Watt[tid];
    __syncthreads();

    const int i = i0 + il;
    const uint32_t* binU = (const uint32_t*)(bin_s + il * 112 * BSX);
    const uint32_t* WbU  = (const uint32_t*)Wb_s;

    // Hoist B fragments for both cc, and the warp-constant P_i fragment values.
    uint32_t bfr[2][2][2][2];   // [cc][Kt][nt][r]
    float2   piv[2][2];         // [cc][nt]
    #pragma unroll
    for (int cc = 0; cc < 2; ++cc) {
        const int nb = (kq * 2 + cc) * 16;
        #pragma unroll
        for (int nt = 0; nt < 2; ++nt) {
            const int kf = nb + nt * 8 + g;
            bfr[cc][0][nt][0] = WbU[(tg)      * WSX + kf];
            bfr[cc][0][nt][1] = WbU[(tg + 4)  * WSX + kf];
            bfr[cc][1][nt][0] = WbU[(tg + 8)  * WSX + kf];
            bfr[cc][1][nt][1] = WbU[(tg + 12) * WSX + kf];
            piv[cc][nt] = *(const float2*)(P_sh + i * PS + nb + nt * 8 + 2 * tg);
        }
    }

    #pragma unroll
    for (int Mt = 0; Mt < 7; ++Mt) {
        const int r0 = Mt * 16 + g;

        // A fragments: loaded once, used by both cc chunks (conflict-free)
        uint32_t a0[4], a1[4];
        a0[0] = binU[(r0)     * BSX + tg];
        a0[1] = binU[(r0 + 8) * BSX + tg];
        a0[2] = binU[(r0)     * BSX + tg + 4];
        a0[3] = binU[(r0 + 8) * BSX + tg + 4];
        a1[0] = binU[(r0)     * BSX + tg + 8];
        a1[1] = binU[(r0 + 8) * BSX + tg + 8];
        a1[2] = binU[(r0)     * BSX + tg + 12];
        a1[3] = binU[(r0 + 8) * BSX + tg + 12];

        float x0 = 0.f, x1 = 0.f;
        #pragma unroll
        for (int cc = 0; cc < 2; ++cc) {
            const int nb = (kq * 2 + cc) * 16;

            float acc[2][4];
            #pragma unroll
            for (int nt = 0; nt < 2; ++nt) {
                const int k0 = nb + nt * 8 + 2 * tg;
                const float2 pj0 = *(const float2*)(P_sh + (r0)     * PS + k0);
                const float2 pj1 = *(const float2*)(P_sh + (r0 + 8) * PS + k0);
                acc[nt][0] = piv[cc][nt].x + pj0.x;
                acc[nt][1] = piv[cc][nt].y + pj0.y;
                acc[nt][2] = piv[cc][nt].x + pj1.x;
                acc[nt][3] = piv[cc][nt].y + pj1.y;
            }

            mma_tf32(acc[0], a0, bfr[cc][0][0]);
            mma_tf32(acc[0], a1, bfr[cc][1][0]);
            mma_tf32(acc[1], a0, bfr[cc][0][1]);
            mma_tf32(acc[1], a1, bfr[cc][1][1]);

            const float2 wav0 = *(const float2*)(wa_sh + nb + 2 * tg);
            const float2 wav1 = *(const float2*)(wa_sh + nb + 8 + 2 * tg);
            x0 = fmaf(fmaxf(acc[0][0], 0.f), wav0.x, x0);
            x0 = fmaf(fmaxf(acc[0][1], 0.f), wav0.y, x0);
            x0 = fmaf(fmaxf(acc[1][0], 0.f), wav1.x, x0);
            x0 = fmaf(fmaxf(acc[1][1], 0.f), wav1.y, x0);
            x1 = fmaf(fmaxf(acc[0][2], 0.f), wav0.x, x1);
            x1 = fmaf(fmaxf(acc[0][3], 0.f), wav0.y, x1);
            x1 = fmaf(fmaxf(acc[1][2], 0.f), wav1.x, x1);
            x1 = fmaf(fmaxf(acc[1][3], 0.f), wav1.y, x1);
        }

        // quad-reduce, stash k-quarter partials for rows r0 and r0+8
        x0 += __shfl_xor_sync(0xFFFFFFFFu, x0, 1);
        x0 += __shfl_xor_sync(0xFFFFFFFFu, x0, 2);
        x1 += __shfl_xor_sync(0xFFFFFFFFu, x1, 1);
        x1 += __shfl_xor_sync(0xFFFFFFFFu, x1, 2);
        if (tg == 0) {
            red[(il * 4 + kq) * 112 + Mt * 16 + g]     = x0;
            red[(il * 4 + kq) * 112 + Mt * 16 + g + 8] = x1;
        }
    }
    __syncthreads();

    // combine k-quarters + sigmoid + store
    if (tid < TIM * 112) {
        const int ii = tid / 112;
        const int j  = tid - ii * 112;
        if (j < NN) {
            const float* r4 = red + ii * 4 * 112 + j;
            const float x = (r4[0] + r4[112]) + (r4[224] + r4[336]);
            const float s = 1.f / (1.f + __expf(-(x + batt[0])));
            d_ATT[(size_t)(b * NN + i0 + ii) * NN + j] = s;
        }
    }
}

// ---------------------------------------------------------------------------
// Kernel B2: g[b,i,k] = sum_j att[b,i,j] * lf[b,j,k].
// ---------------------------------------------------------------------------
#define TI2 10
#define KB2_SMEM (NN * HH * 4 + TI2 * NN * 4)   // 55200 B

__global__ __launch_bounds__(128) void kB2(const float* __restrict__ lf) {
    extern __shared__ float sm2[];
    float* L_sh = sm2;               // [NN][HH]
    float* s_sh = sm2 + NN * HH;     // [TI2][NN]

    const int b   = blockIdx.x / (NN / TI2);
    const int i0  = (blockIdx.x % (NN / TI2)) * TI2;
    const int tid = threadIdx.x;

    {
        const float4* Ls = (const float4*)(lf + (size_t)b * NN * HH);
        float4* Ld = (float4*)L_sh;
        for (int t = tid; t < NN * HH / 4; t += 128) Ld[t] = Ls[t];
        const float* As = d_ATT + (size_t)(b * NN + i0) * NN;
        for (int t = tid; t < TI2 * NN; t += 128) s_sh[t] = As[t];
    }
    __syncthreads();

    const int k = tid;
    float acc[TI2];
    #pragma unroll
    for (int ii = 0; ii < TI2; ++ii) acc[ii] = 0.f;

    #pragma unroll 2
    for (int j = 0; j < NN; ++j) {
        const float lv = L_sh[j * HH + k];
        #pragma unroll
        for (int ii = 0; ii < TI2; ++ii)
            acc[ii] = fmaf(s_sh[ii * NN + j], lv, acc[ii]);
    }
    #pragma unroll
    for (int ii = 0; ii < TI2; ++ii)
        d_G[(size_t)(b * NN + i0 + ii) * HH + k] = acc[ii];
}

// ---------------------------------------------------------------------------
// Kernel C: gather epilogue. 4 e per 256-thread block; streaming stores.
// ---------------------------------------------------------------------------
__global__ __launch_bounds__(256) void kC(const float* __restrict__ lf,
                                          const int* __restrict__ idx,
                                          float* __restrict__ out) {
    const int e    = blockIdx.x * 4 + (threadIdx.x >> 6);
    const int half = (threadIdx.x >> 5) & 1;
    const int lane = threadIdx.x & 31;

    int b = idx[e * 3 + 0];
    int i = idx[e * 3 + 1];
    int j = idx[e * 3 + 2];
    b = min(max(b, 0), BB - 1);
    i = min(max(i, 0), NN - 1);
    j = min(max(j, 0), NN - 1);

    const size_t ri = ((size_t)b * NN + i) * (HH / 4);
    const size_t rj = ((size_t)b * NN + j) * (HH / 4);
    float4* o = (float4*)out;

    if (half == 0) {
        const float4* L = (const float4*)lf;
        const float4 a = __ldg(L + ri + lane), c = __ldg(L + rj + lane);
        float4 r; r.x = a.x + c.x; r.y = a.y + c.y; r.z = a.z + c.z; r.w = a.w + c.w;
        __stcs(o + (size_t)e * 32 + lane, r);
    } else {
        const float4* G4 = (const float4*)d_G;
        const float4 a = __ldg(G4 + ri + lane), c = __ldg(G4 + rj + lane);
        float4 r; r.x = a.x + c.x; r.y = a.y + c.y; r.z = a.z + c.z; r.w = a.w + c.w;
        __stcs(o + (size_t)EE * 32 + (size_t)e * 32 + lane, r);
    }
}

// ---------------------------------------------------------------------------
extern "C" void kernel_launch(void* const* d_in, const int* in_sizes, int n_in,
                              void* d_out, int out_size) {
    const float* lf   = (const float*)d_in[0];
    const float* bin  = (const float*)d_in[1];
    const int*   sidx = (const int*)d_in[2];
    const float* Wap  = (const float*)d_in[3];
    const float* Wb   = (const float*)d_in[4];
    const float* bb   = (const float*)d_in[5];
    const float* Watt = (const float*)d_in[6];
    const float* batt = (const float*)d_in[7];
    float*       out  = (float*)d_out;

    static bool attr_set = false;
    if (!attr_set) {
        cudaFuncSetAttribute(kB1m, cudaFuncAttributeMaxDynamicSharedMemorySize, KB1M_SMEM);
        cudaFuncSetAttribute(kB2,  cudaFuncAttributeMaxDynamicSharedMemorySize, KB2_SMEM);
        attr_set = true;
    }

    kA  <<<BB * NN / RA, 512>>>(lf, Wap, bb);
    kB1m<<<BB * (NN / TIM), 512, KB1M_SMEM>>>(bin, Wb, Watt, batt);
    kB2 <<<BB * (NN / TI2), 128, KB2_SMEM>>>(lf);
    kC  <<<EE / 4, 256>>>(lf, sidx, out);
}